// round 2
// baseline (speedup 1.0000x reference)
#include <cuda_runtime.h>
#include <math.h>

// Problem constants
#define BB 2
#define NN 2048
#define EE 1024
#define HH 16
#define HD 64
#define ROWS (BB*NN)          // 4096

// Scratch (device globals; no allocations allowed)
__device__ float g_k[BB*HH*NN*HD];
__device__ float g_q[BB*HH*NN*HD];
__device__ float g_v[BB*HH*NN*HD];
__device__ float g_sa[BB*NN*EE];

// ---------------------------------------------------------------------------
// QKV GEMM: C[4096, 3072] = x[4096,1024] @ Wqkv (head-blocked), + bias,
// scattered into g_k/g_q/g_v with layout [B,H,N,HD].
// Tile: 128(M) x 64(N), BK=16, 128 threads, 8x8 microtile (split halves).
// A 64-col tile always lies inside one head (192 = 3*64) and one K/Q/V segment.
// ---------------------------------------------------------------------------
__global__ __launch_bounds__(128) void qkv_gemm(const float* __restrict__ x,
                                                const float* __restrict__ Wqkv,
                                                const float* __restrict__ bqkv)
{
    const int tid = threadIdx.x;
    const int c0  = blockIdx.x * 64;
    const int r0  = blockIdx.y * 128;
    const int h   = c0 / 192;
    const int f0  = c0 % 192;     // 0, 64 or 128 -> segment
    const int seg = f0 >> 6;

    __shared__ float As[16][132];   // k-major, padded
    __shared__ float Bs[16][64];

    const int tx = tid & 7;
    const int ty = tid >> 3;

    float acc[8][8];
#pragma unroll
    for (int i = 0; i < 8; i++)
#pragma unroll
        for (int j = 0; j < 8; j++) acc[i][j] = 0.f;

    const float* Aptr = x + (size_t)r0 * EE;
    const float* Bptr = Wqkv + (size_t)h * EE * 192 + f0;

    for (int k0 = 0; k0 < EE; k0 += 16) {
        // A tile 128x16, transposed into As[k][m]
#pragma unroll
        for (int i = 0; i < 4; i++) {
            int f  = tid * 4 + i * 512;
            int ar = f >> 4;
            int ak = f & 15;
            float4 v = *(const float4*)(Aptr + (size_t)ar * EE + k0 + ak);
            As[ak + 0][ar] = v.x;
            As[ak + 1][ar] = v.y;
            As[ak + 2][ar] = v.z;
            As[ak + 3][ar] = v.w;
        }
        // B tile 16x64
#pragma unroll
        for (int i = 0; i < 2; i++) {
            int fi = tid * 2 + i;
            int bk = fi >> 4;
            int bc = (fi & 15) * 4;
            *(float4*)&Bs[bk][bc] = *(const float4*)(Bptr + (size_t)(k0 + bk) * 192 + bc);
        }
        __syncthreads();

#pragma unroll
        for (int kk = 0; kk < 16; kk++) {
            float a[8], b[8];
            *(float4*)&a[0] = *(const float4*)&As[kk][ty * 4];
            *(float4*)&a[4] = *(const float4*)&As[kk][64 + ty * 4];
            *(float4*)&b[0] = *(const float4*)&Bs[kk][tx * 4];
            *(float4*)&b[4] = *(const float4*)&Bs[kk][32 + tx * 4];
#pragma unroll
            for (int i = 0; i < 8; i++)
#pragma unroll
                for (int j = 0; j < 8; j++)
                    acc[i][j] += a[i] * b[j];
        }
        __syncthreads();
    }

    float* dst = (seg == 0) ? g_k : (seg == 1) ? g_q : g_v;

    float bias[8];
#pragma unroll
    for (int j = 0; j < 8; j++) {
        int col = (j < 4) ? tx * 4 + j : 32 + tx * 4 + (j - 4);
        bias[j] = bqkv[h * 192 + f0 + col];
    }

#pragma unroll
    for (int i = 0; i < 8; i++) {
        int row = (i < 4) ? ty * 4 + i : 64 + ty * 4 + (i - 4);
        int r = r0 + row;
        int b = r >> 11;       // / NN
        int n = r & (NN - 1);
        size_t base = ((size_t)(b * HH + h) * NN + n) * HD;
#pragma unroll
        for (int j = 0; j < 8; j++) {
            int col = (j < 4) ? tx * 4 + j : 32 + tx * 4 + (j - 4);
            dst[base + col] = acc[i][j] + bias[j];
        }
    }
}

// ---------------------------------------------------------------------------
// Causal flash attention, fp32. One block per (q-tile of 64 rows, b*h).
// 256 threads = 64 rows x 4 sub-threads. Online softmax.
// smem: Qs/Ks/Vs stride 68 (bank-safe), Ps stride 68.
// ---------------------------------------------------------------------------
__global__ __launch_bounds__(256) void attn_kernel()
{
    extern __shared__ float smem[];
    float* Qs = smem;               // 64*68
    float* Ks = Qs + 64 * 68;
    float* Vs = Ks + 64 * 68;
    float* Ps = Vs + 64 * 68;

    const int tid = threadIdx.x;
    const int qt  = blockIdx.x;     // q tile (0..31)
    const int bh  = blockIdx.y;     // b*H + h
    const int row = tid >> 2;       // 0..63
    const int sub = tid & 3;        // 0..3

    const float* qptr = g_q + ((size_t)bh * NN + (size_t)qt * 64) * HD;
    const float* kptr = g_k + (size_t)bh * NN * HD;
    const float* vptr = g_v + (size_t)bh * NN * HD;

    const float scale = 0.125f;     // 1/sqrt(64)
#pragma unroll
    for (int i = 0; i < 4; i++) {
        int f = (tid + i * 256) * 4;
        int r = f >> 6, d = f & 63;
        float4 v = *(const float4*)(qptr + f);
        v.x *= scale; v.y *= scale; v.z *= scale; v.w *= scale;
        *(float4*)&Qs[r * 68 + d] = v;
    }

    float m_run = -INFINITY;
    float l_run = 0.0f;
    float acc[16];
#pragma unroll
    for (int i = 0; i < 16; i++) acc[i] = 0.f;

    const unsigned FULL = 0xffffffffu;

    for (int jt = 0; jt <= qt; jt++) {
#pragma unroll
        for (int i = 0; i < 4; i++) {
            int f = (tid + i * 256) * 4;
            int r = f >> 6, d = f & 63;
            *(float4*)&Ks[r * 68 + d] = *(const float4*)(kptr + (size_t)jt * 64 * HD + f);
            *(float4*)&Vs[r * 68 + d] = *(const float4*)(vptr + (size_t)jt * 64 * HD + f);
        }
        __syncthreads();

        // S = Q K^T (this thread: 16 cols jc = sub + 4*jj)
        float s[16];
#pragma unroll
        for (int jj = 0; jj < 16; jj++) s[jj] = 0.f;
#pragma unroll
        for (int dd = 0; dd < 16; dd++) {
            float4 q4 = *(const float4*)&Qs[row * 68 + dd * 4];
#pragma unroll
            for (int jj = 0; jj < 16; jj++) {
                int jc = sub + jj * 4;
                float4 k4 = *(const float4*)&Ks[jc * 68 + dd * 4];
                s[jj] += q4.x * k4.x + q4.y * k4.y + q4.z * k4.z + q4.w * k4.w;
            }
        }

        if (jt == qt) {
#pragma unroll
            for (int jj = 0; jj < 16; jj++) {
                int jc = sub + jj * 4;
                if (jc > row) s[jj] = -INFINITY;
            }
        }

        // online softmax
        float mt = s[0];
#pragma unroll
        for (int jj = 1; jj < 16; jj++) mt = fmaxf(mt, s[jj]);
        mt = fmaxf(mt, __shfl_xor_sync(FULL, mt, 1));
        mt = fmaxf(mt, __shfl_xor_sync(FULL, mt, 2));

        float m_new = fmaxf(m_run, mt);
        float corr  = __expf(m_run - m_new);

        float p[16];
        float psum = 0.f;
#pragma unroll
        for (int jj = 0; jj < 16; jj++) {
            p[jj] = __expf(s[jj] - m_new);
            psum += p[jj];
        }
        psum += __shfl_xor_sync(FULL, psum, 1);
        psum += __shfl_xor_sync(FULL, psum, 2);

        l_run = l_run * corr + psum;
        m_run = m_new;
#pragma unroll
        for (int i = 0; i < 16; i++) acc[i] *= corr;

#pragma unroll
        for (int jj = 0; jj < 16; jj++)
            Ps[row * 68 + sub + jj * 4] = p[jj];
        __syncthreads();

        // O += P V  (this thread: d chunks sub*4 + 16*c)
#pragma unroll 4
        for (int j = 0; j < 64; j++) {
            float pj = Ps[row * 68 + j];
#pragma unroll
            for (int c = 0; c < 4; c++) {
                float4 v4 = *(const float4*)&Vs[j * 68 + sub * 4 + c * 16];
                acc[c * 4 + 0] += pj * v4.x;
                acc[c * 4 + 1] += pj * v4.y;
                acc[c * 4 + 2] += pj * v4.z;
                acc[c * 4 + 3] += pj * v4.w;
            }
        }
        __syncthreads();
    }

    const float inv_l = 1.0f / l_run;
    const int qg = qt * 64 + row;
    const int b = bh >> 4;
    const int h = bh & 15;
    float* optr = g_sa + ((size_t)b * NN + qg) * EE + h * HD;
#pragma unroll
    for (int c = 0; c < 4; c++) {
        float4 o;
        o.x = acc[c * 4 + 0] * inv_l;
        o.y = acc[c * 4 + 1] * inv_l;
        o.z = acc[c * 4 + 2] * inv_l;
        o.w = acc[c * 4 + 3] * inv_l;
        *(float4*)&optr[sub * 4 + c * 16] = o;
    }
}

// ---------------------------------------------------------------------------
// Output GEMM: out[4096,1024] = g_sa @ Wout + bout
// Same tiling as qkv_gemm.
// ---------------------------------------------------------------------------
__global__ __launch_bounds__(128) void out_gemm(const float* __restrict__ Wout,
                                                const float* __restrict__ bout,
                                                float* __restrict__ out)
{
    const int tid = threadIdx.x;
    const int c0  = blockIdx.x * 64;
    const int r0  = blockIdx.y * 128;

    __shared__ float As[16][132];
    __shared__ float Bs[16][64];

    const int tx = tid & 7;
    const int ty = tid >> 3;

    float acc[8][8];
#pragma unroll
    for (int i = 0; i < 8; i++)
#pragma unroll
        for (int j = 0; j < 8; j++) acc[i][j] = 0.f;

    const float* Aptr = g_sa + (size_t)r0 * EE;
    const float* Bptr = Wout + c0;

    for (int k0 = 0; k0 < EE; k0 += 16) {
#pragma unroll
        for (int i = 0; i < 4; i++) {
            int f  = tid * 4 + i * 512;
            int ar = f >> 4;
            int ak = f & 15;
            float4 v = *(const float4*)(Aptr + (size_t)ar * EE + k0 + ak);
            As[ak + 0][ar] = v.x;
            As[ak + 1][ar] = v.y;
            As[ak + 2][ar] = v.z;
            As[ak + 3][ar] = v.w;
        }
#pragma unroll
        for (int i = 0; i < 2; i++) {
            int fi = tid * 2 + i;
            int bk = fi >> 4;
            int bc = (fi & 15) * 4;
            *(float4*)&Bs[bk][bc] = *(const float4*)(Bptr + (size_t)(k0 + bk) * EE + bc);
        }
        __syncthreads();

#pragma unroll
        for (int kk = 0; kk < 16; kk++) {
            float a[8], b[8];
            *(float4*)&a[0] = *(const float4*)&As[kk][ty * 4];
            *(float4*)&a[4] = *(const float4*)&As[kk][64 + ty * 4];
            *(float4*)&b[0] = *(const float4*)&Bs[kk][tx * 4];
            *(float4*)&b[4] = *(const float4*)&Bs[kk][32 + tx * 4];
#pragma unroll
            for (int i = 0; i < 8; i++)
#pragma unroll
                for (int j = 0; j < 8; j++)
                    acc[i][j] += a[i] * b[j];
        }
        __syncthreads();
    }

    float bias[8];
#pragma unroll
    for (int j = 0; j < 8; j++) {
        int col = (j < 4) ? tx * 4 + j : 32 + tx * 4 + (j - 4);
        bias[j] = bout[c0 + col];
    }

#pragma unroll
    for (int i = 0; i < 8; i++) {
        int row = (i < 4) ? ty * 4 + i : 64 + ty * 4 + (i - 4);
        size_t r = (size_t)(r0 + row);
#pragma unroll
        for (int j = 0; j < 8; j++) {
            int col = (j < 4) ? tx * 4 + j : 32 + tx * 4 + (j - 4);
            out[r * EE + c0 + col] = acc[i][j] + bias[j];
        }
    }
}

extern "C" void kernel_launch(void* const* d_in, const int* in_sizes, int n_in,
                              void* d_out, int out_size)
{
    const float* x    = (const float*)d_in[0];
    const float* Wqkv = (const float*)d_in[1];
    const float* bqkv = (const float*)d_in[2];
    const float* Wout = (const float*)d_in[3];
    const float* bout = (const float*)d_in[4];
    float* out = (float*)d_out;

    // 1) QKV projection
    {
        dim3 grid(3 * HH * HD / 64, ROWS / 128);   // (48, 32)
        qkv_gemm<<<grid, 128>>>(x, Wqkv, bqkv);
    }

    // 2) Causal attention
    {
        int smem_bytes = 4 * 64 * 68 * (int)sizeof(float);  // 69632
        cudaFuncSetAttribute(attn_kernel,
                             cudaFuncAttributeMaxDynamicSharedMemorySize, smem_bytes);
        dim3 grid(NN / 64, BB * HH);               // (32, 32)
        attn_kernel<<<grid, 256, smem_bytes>>>();
    }

    // 3) Output projection
    {
        dim3 grid(EE / 64, ROWS / 128);            // (16, 32)
        out_gemm<<<grid, 128>>>(Wout, bout, out);
    }
}

// round 7
// speedup vs baseline: 1.3691x; 1.3691x over previous
#include <cuda_runtime.h>
#include <math.h>

// Problem constants
#define BB 2
#define NN 2048
#define EE 1024
#define HH 16
#define HD 64
#define ROWS (BB*NN)          // 4096

// Scratch (device globals; no allocations allowed)
__device__ float g_k[BB*HH*NN*HD];
__device__ float g_q[BB*HH*NN*HD];
__device__ float g_v[BB*HH*NN*HD];
__device__ float g_sa[BB*NN*EE];

// ---------------------------------------------------------------------------
// QKV GEMM: C[4096, 3072] = x[4096,1024] @ Wqkv (head-blocked), + bias,
// scattered into g_k/g_q/g_v with layout [B,H,N,HD].
// Tile: 128(M) x 64(N), BK=16, 128 threads, 8x8 microtile, double-buffered.
// ---------------------------------------------------------------------------
__global__ __launch_bounds__(128) void qkv_gemm(const float* __restrict__ x,
                                                const float* __restrict__ Wqkv,
                                                const float* __restrict__ bqkv)
{
    const int tid = threadIdx.x;
    const int c0  = blockIdx.x * 64;
    const int r0  = blockIdx.y * 128;
    const int h   = c0 / 192;
    const int f0  = c0 % 192;     // 0, 64 or 128 -> segment
    const int seg = f0 >> 6;

    __shared__ float As[2][16][132];   // k-major, padded
    __shared__ float Bs[2][16][64];

    const int tx = tid & 7;
    const int ty = tid >> 3;

    float acc[8][8];
#pragma unroll
    for (int i = 0; i < 8; i++)
#pragma unroll
        for (int j = 0; j < 8; j++) acc[i][j] = 0.f;

    const float* Aptr = x + (size_t)r0 * EE;
    const float* Bptr = Wqkv + (size_t)h * EE * 192 + f0;

    // prologue: stage 0
    {
#pragma unroll
        for (int i = 0; i < 4; i++) {
            int f  = tid * 4 + i * 512;
            int ar = f >> 4;
            int ak = f & 15;
            float4 v = *(const float4*)(Aptr + (size_t)ar * EE + ak);
            As[0][ak + 0][ar] = v.x;
            As[0][ak + 1][ar] = v.y;
            As[0][ak + 2][ar] = v.z;
            As[0][ak + 3][ar] = v.w;
        }
#pragma unroll
        for (int i = 0; i < 2; i++) {
            int fi = tid * 2 + i;
            int bk = fi >> 4;
            int bc = (fi & 15) * 4;
            *(float4*)&Bs[0][bk][bc] = *(const float4*)(Bptr + (size_t)bk * 192 + bc);
        }
    }
    __syncthreads();

    for (int it = 0; it < 64; it++) {
        const int cur = it & 1;
        const int nxt = cur ^ 1;

        float4 pa[4];
        float4 pb[2];
        if (it < 63) {
            const int k0 = (it + 1) * 16;
#pragma unroll
            for (int i = 0; i < 4; i++) {
                int f  = tid * 4 + i * 512;
                int ar = f >> 4;
                int ak = f & 15;
                pa[i] = *(const float4*)(Aptr + (size_t)ar * EE + k0 + ak);
            }
#pragma unroll
            for (int i = 0; i < 2; i++) {
                int fi = tid * 2 + i;
                int bk = fi >> 4;
                int bc = (fi & 15) * 4;
                pb[i] = *(const float4*)(Bptr + (size_t)(k0 + bk) * 192 + bc);
            }
        }

#pragma unroll
        for (int kk = 0; kk < 16; kk++) {
            float a[8], b[8];
            *(float4*)&a[0] = *(const float4*)&As[cur][kk][ty * 4];
            *(float4*)&a[4] = *(const float4*)&As[cur][kk][64 + ty * 4];
            *(float4*)&b[0] = *(const float4*)&Bs[cur][kk][tx * 4];
            *(float4*)&b[4] = *(const float4*)&Bs[cur][kk][32 + tx * 4];
#pragma unroll
            for (int i = 0; i < 8; i++)
#pragma unroll
                for (int j = 0; j < 8; j++)
                    acc[i][j] += a[i] * b[j];
        }

        if (it < 63) {
#pragma unroll
            for (int i = 0; i < 4; i++) {
                int f  = tid * 4 + i * 512;
                int ar = f >> 4;
                int ak = f & 15;
                As[nxt][ak + 0][ar] = pa[i].x;
                As[nxt][ak + 1][ar] = pa[i].y;
                As[nxt][ak + 2][ar] = pa[i].z;
                As[nxt][ak + 3][ar] = pa[i].w;
            }
#pragma unroll
            for (int i = 0; i < 2; i++) {
                int fi = tid * 2 + i;
                int bk = fi >> 4;
                int bc = (fi & 15) * 4;
                *(float4*)&Bs[nxt][bk][bc] = pb[i];
            }
        }
        __syncthreads();
    }

    float* dst = (seg == 0) ? g_k : (seg == 1) ? g_q : g_v;

    float bias[8];
#pragma unroll
    for (int j = 0; j < 8; j++) {
        int col = (j < 4) ? tx * 4 + j : 32 + tx * 4 + (j - 4);
        bias[j] = bqkv[h * 192 + f0 + col];
    }

#pragma unroll
    for (int i = 0; i < 8; i++) {
        int row = (i < 4) ? ty * 4 + i : 64 + ty * 4 + (i - 4);
        int r = r0 + row;
        int b = r >> 11;       // / NN
        int n = r & (NN - 1);
        size_t base = ((size_t)(b * HH + h) * NN + n) * HD;
#pragma unroll
        for (int j = 0; j < 8; j++) {
            int col = (j < 4) ? tx * 4 + j : 32 + tx * 4 + (j - 4);
            dst[base + col] = acc[i][j] + bias[j];
        }
    }
}

// ---------------------------------------------------------------------------
// Causal flash attention, fp32. One block per (q-tile of 128 rows, b*h).
// 128 threads, 8x8 microtiles with strided ownership:
//   rows r = ty + 16*i (ty=tid/8), cols j/d = tx + 8*jj (tx=tid%8)
// -> all LDS conflict-free. smem 104.4KB -> 2 blocks/SM.
// ---------------------------------------------------------------------------
__global__ __launch_bounds__(128) void attn_kernel()
{
    extern __shared__ float smem[];
    float* Qs = smem;                 // [128][68]
    float* Ks = Qs + 128 * 68;        // [64][68]
    float* Vs = Ks + 64 * 68;         // [64][68]
    float* Ps = Vs + 64 * 68;         // [128][68]

    const int tid = threadIdx.x;
    const int ty  = tid >> 3;         // 0..15
    const int tx  = tid & 7;          // 0..7
    const int qt  = (int)gridDim.x - 1 - (int)blockIdx.x;  // heavy blocks first
    const int bh  = blockIdx.y;

    const float* qptr = g_q + ((size_t)bh * NN + (size_t)qt * 128) * HD;
    const float* kptr = g_k + (size_t)bh * NN * HD;
    const float* vptr = g_v + (size_t)bh * NN * HD;

    const float scale = 0.125f;       // 1/sqrt(64)
#pragma unroll
    for (int i = 0; i < 16; i++) {
        int f = (tid + i * 128) * 4;
        int r = f >> 6, d = f & 63;
        float4 v = *(const float4*)(qptr + f);
        v.x *= scale; v.y *= scale; v.z *= scale; v.w *= scale;
        *(float4*)&Qs[r * 68 + d] = v;
    }

    float o[8][8];
    float m_run[8], l_run[8];
#pragma unroll
    for (int i = 0; i < 8; i++) {
        m_run[i] = -INFINITY;
        l_run[i] = 0.f;
#pragma unroll
        for (int d = 0; d < 8; d++) o[i][d] = 0.f;
    }

    const unsigned FULL = 0xffffffffu;
    const int jt_end = 2 * qt + 1;

    for (int jt = 0; jt <= jt_end; jt++) {
        __syncthreads();   // prev iter's PV readers done with Ks/Vs/Ps

        // load K, V tiles (64x64 each)
#pragma unroll
        for (int i = 0; i < 8; i++) {
            int f = (tid + i * 128) * 4;
            int r = f >> 6, d = f & 63;
            *(float4*)&Ks[r * 68 + d] = *(const float4*)(kptr + (size_t)jt * 64 * HD + f);
            *(float4*)&Vs[r * 68 + d] = *(const float4*)(vptr + (size_t)jt * 64 * HD + f);
        }
        __syncthreads();

        // S = Q K^T  : 8x8 per thread
        float s[8][8];
#pragma unroll
        for (int i = 0; i < 8; i++)
#pragma unroll
            for (int jj = 0; jj < 8; jj++) s[i][jj] = 0.f;

#pragma unroll 4
        for (int dc = 0; dc < 16; dc++) {
            float4 a4[8];
#pragma unroll
            for (int i = 0; i < 8; i++)
                a4[i] = *(const float4*)&Qs[(ty + 16 * i) * 68 + dc * 4];
#pragma unroll
            for (int jj = 0; jj < 8; jj++) {
                float4 b4 = *(const float4*)&Ks[(tx + 8 * jj) * 68 + dc * 4];
#pragma unroll
                for (int i = 0; i < 8; i++)
                    s[i][jj] += a4[i].x * b4.x + a4[i].y * b4.y
                              + a4[i].z * b4.z + a4[i].w * b4.w;
            }
        }

        // causal mask (only last two tiles can straddle the diagonal)
        if (jt >= 2 * qt) {
#pragma unroll
            for (int i = 0; i < 8; i++) {
                int rg = qt * 128 + ty + 16 * i;
#pragma unroll
                for (int jj = 0; jj < 8; jj++) {
                    int jg = jt * 64 + tx + 8 * jj;
                    if (jg > rg) s[i][jj] = -INFINITY;
                }
            }
        }

        // online softmax per owned row; row group = 8 contiguous lanes (same ty)
#pragma unroll
        for (int i = 0; i < 8; i++) {
            float mt = s[i][0];
#pragma unroll
            for (int jj = 1; jj < 8; jj++) mt = fmaxf(mt, s[i][jj]);
            mt = fmaxf(mt, __shfl_xor_sync(FULL, mt, 1));
            mt = fmaxf(mt, __shfl_xor_sync(FULL, mt, 2));
            mt = fmaxf(mt, __shfl_xor_sync(FULL, mt, 4));

            float m_new = fmaxf(m_run[i], mt);
            float corr  = __expf(m_run[i] - m_new);

            float psum = 0.f;
#pragma unroll
            for (int jj = 0; jj < 8; jj++) {
                s[i][jj] = __expf(s[i][jj] - m_new);
                psum += s[i][jj];
            }
            psum += __shfl_xor_sync(FULL, psum, 1);
            psum += __shfl_xor_sync(FULL, psum, 2);
            psum += __shfl_xor_sync(FULL, psum, 4);

            l_run[i] = l_run[i] * corr + psum;
            m_run[i] = m_new;
#pragma unroll
            for (int d = 0; d < 8; d++) o[i][d] *= corr;
#pragma unroll
            for (int jj = 0; jj < 8; jj++)
                Ps[(ty + 16 * i) * 68 + tx + 8 * jj] = s[i][jj];
        }
        __syncthreads();

        // O += P V
#pragma unroll 2
        for (int j = 0; j < 64; j++) {
            float vv[8];
#pragma unroll
            for (int d = 0; d < 8; d++)
                vv[d] = Vs[j * 68 + tx + 8 * d];
#pragma unroll
            for (int i = 0; i < 8; i++) {
                float pj = Ps[(ty + 16 * i) * 68 + j];
#pragma unroll
                for (int d = 0; d < 8; d++)
                    o[i][d] += pj * vv[d];
            }
        }
    }

    // epilogue: normalize + scatter to g_sa [B, N, E]
    const int b = bh >> 4;
    const int h = bh & 15;
#pragma unroll
    for (int i = 0; i < 8; i++) {
        const float inv_l = 1.0f / l_run[i];
        const int qg = qt * 128 + ty + 16 * i;
        float* op = g_sa + ((size_t)b * NN + qg) * EE + h * HD;
#pragma unroll
        for (int d = 0; d < 8; d++)
            op[tx + 8 * d] = o[i][d] * inv_l;
    }
}

// ---------------------------------------------------------------------------
// Output GEMM: out[4096,1024] = g_sa @ Wout + bout (double-buffered)
// ---------------------------------------------------------------------------
__global__ __launch_bounds__(128) void out_gemm(const float* __restrict__ Wout,
                                                const float* __restrict__ bout,
                                                float* __restrict__ out)
{
    const int tid = threadIdx.x;
    const int c0  = blockIdx.x * 64;
    const int r0  = blockIdx.y * 128;

    __shared__ float As[2][16][132];
    __shared__ float Bs[2][16][64];

    const int tx = tid & 7;
    const int ty = tid >> 3;

    float acc[8][8];
#pragma unroll
    for (int i = 0; i < 8; i++)
#pragma unroll
        for (int j = 0; j < 8; j++) acc[i][j] = 0.f;

    const float* Aptr = g_sa + (size_t)r0 * EE;
    const float* Bptr = Wout + c0;

    {
#pragma unroll
        for (int i = 0; i < 4; i++) {
            int f  = tid * 4 + i * 512;
            int ar = f >> 4;
            int ak = f & 15;
            float4 v = *(const float4*)(Aptr + (size_t)ar * EE + ak);
            As[0][ak + 0][ar] = v.x;
            As[0][ak + 1][ar] = v.y;
            As[0][ak + 2][ar] = v.z;
            As[0][ak + 3][ar] = v.w;
        }
#pragma unroll
        for (int i = 0; i < 2; i++) {
            int fi = tid * 2 + i;
            int bk = fi >> 4;
            int bc = (fi & 15) * 4;
            *(float4*)&Bs[0][bk][bc] = *(const float4*)(Bptr + (size_t)bk * EE + bc);
        }
    }
    __syncthreads();

    for (int it = 0; it < 64; it++) {
        const int cur = it & 1;
        const int nxt = cur ^ 1;

        float4 pa[4];
        float4 pb[2];
        if (it < 63) {
            const int k0 = (it + 1) * 16;
#pragma unroll
            for (int i = 0; i < 4; i++) {
                int f  = tid * 4 + i * 512;
                int ar = f >> 4;
                int ak = f & 15;
                pa[i] = *(const float4*)(Aptr + (size_t)ar * EE + k0 + ak);
            }
#pragma unroll
            for (int i = 0; i < 2; i++) {
                int fi = tid * 2 + i;
                int bk = fi >> 4;
                int bc = (fi & 15) * 4;
                pb[i] = *(const float4*)(Bptr + (size_t)(k0 + bk) * EE + bc);
            }
        }

#pragma unroll
        for (int kk = 0; kk < 16; kk++) {
            float a[8], b[8];
            *(float4*)&a[0] = *(const float4*)&As[cur][kk][ty * 4];
            *(float4*)&a[4] = *(const float4*)&As[cur][kk][64 + ty * 4];
            *(float4*)&b[0] = *(const float4*)&Bs[cur][kk][tx * 4];
            *(float4*)&b[4] = *(const float4*)&Bs[cur][kk][32 + tx * 4];
#pragma unroll
            for (int i = 0; i < 8; i++)
#pragma unroll
                for (int j = 0; j < 8; j++)
                    acc[i][j] += a[i] * b[j];
        }

        if (it < 63) {
#pragma unroll
            for (int i = 0; i < 4; i++) {
                int f  = tid * 4 + i * 512;
                int ar = f >> 4;
                int ak = f & 15;
                As[nxt][ak + 0][ar] = pa[i].x;
                As[nxt][ak + 1][ar] = pa[i].y;
                As[nxt][ak + 2][ar] = pa[i].z;
                As[nxt][ak + 3][ar] = pa[i].w;
            }
#pragma unroll
            for (int i = 0; i < 2; i++) {
                int fi = tid * 2 + i;
                int bk = fi >> 4;
                int bc = (fi & 15) * 4;
                *(float4*)&Bs[nxt][bk][bc] = pb[i];
            }
        }
        __syncthreads();
    }

    float bias[8];
#pragma unroll
    for (int j = 0; j < 8; j++) {
        int col = (j < 4) ? tx * 4 + j : 32 + tx * 4 + (j - 4);
        bias[j] = bout[c0 + col];
    }

#pragma unroll
    for (int i = 0; i < 8; i++) {
        int row = (i < 4) ? ty * 4 + i : 64 + ty * 4 + (i - 4);
        size_t r = (size_t)(r0 + row);
#pragma unroll
        for (int j = 0; j < 8; j++) {
            int col = (j < 4) ? tx * 4 + j : 32 + tx * 4 + (j - 4);
            out[r * EE + c0 + col] = acc[i][j] + bias[j];
        }
    }
}

extern "C" void kernel_launch(void* const* d_in, const int* in_sizes, int n_in,
                              void* d_out, int out_size)
{
    const float* x    = (const float*)d_in[0];
    const float* Wqkv = (const float*)d_in[1];
    const float* bqkv = (const float*)d_in[2];
    const float* Wout = (const float*)d_in[3];
    const float* bout = (const float*)d_in[4];
    float* out = (float*)d_out;

    // 1) QKV projection
    {
        dim3 grid(3 * HH * HD / 64, ROWS / 128);   // (48, 32)
        qkv_gemm<<<grid, 128>>>(x, Wqkv, bqkv);
    }

    // 2) Causal attention
    {
        int smem_bytes = (128 + 64 + 64 + 128) * 68 * (int)sizeof(float);  // 104448
        cudaFuncSetAttribute(attn_kernel,
                             cudaFuncAttributeMaxDynamicSharedMemorySize, smem_bytes);
        dim3 grid(NN / 128, BB * HH);              // (16, 32)
        attn_kernel<<<grid, 128, smem_bytes>>>();
    }

    // 3) Output projection
    {
        dim3 grid(EE / 64, ROWS / 128);            // (16, 32)
        out_gemm<<<grid, 128>>>(Wout, bout, out);
    }
}

// round 10
// speedup vs baseline: 2.2285x; 1.6277x over previous
#include <cuda_runtime.h>
#include <math.h>
#include <stdint.h>

// Problem constants
#define BB 2
#define NN 2048
#define EE 1024
#define HH 16
#define HD 64
#define ROWS (BB*NN)          // 4096
#define FF (3*HH*HD)          // 3072

// Scratch (device globals; no allocations allowed)
__device__ float g_k[BB*HH*NN*HD];
__device__ float g_q[BB*HH*NN*HD];
__device__ float g_v[BB*HH*NN*HD];
__device__ float g_sa[BB*NN*EE];
__device__ float g_xr[ROWS*EE];        // x rounded to tf32
__device__ float g_wtq[FF*EE];         // Wqkv transposed [F][E], tf32-rounded
__device__ float g_wto[EE*EE];         // Wout transposed [n][k], tf32-rounded

// ---------------------------------------------------------------------------
// helpers
// ---------------------------------------------------------------------------
__device__ __forceinline__ float to_tf32(float x) {
    uint32_t u;
    asm("cvt.rna.tf32.f32 %0, %1;" : "=r"(u) : "f"(x));
    return __uint_as_float(u);
}
__device__ __forceinline__ uint32_t s2u(const void* p) {
    uint32_t a;
    asm("{ .reg .u64 t; cvta.to.shared.u64 t, %1; cvt.u32.u64 %0, t; }" : "=r"(a) : "l"(p));
    return a;
}

#define CP_ASYNC16(dst_u32, src_ptr) \
    asm volatile("cp.async.cg.shared.global [%0], [%1], 16;" :: "r"(dst_u32), "l"(src_ptr))
#define CP_COMMIT() asm volatile("cp.async.commit_group;" ::: "memory")
#define CP_WAIT1()  asm volatile("cp.async.wait_group 1;" ::: "memory")
#define CP_WAIT0()  asm volatile("cp.async.wait_group 0;" ::: "memory")

__device__ __forceinline__ void mma_tf32_16n8k8(float* c, const uint32_t* a, const uint32_t* b) {
    asm volatile(
        "mma.sync.aligned.m16n8k8.row.col.f32.tf32.tf32.f32 "
        "{%0,%1,%2,%3}, {%4,%5,%6,%7}, {%8,%9}, {%0,%1,%2,%3};"
        : "+f"(c[0]), "+f"(c[1]), "+f"(c[2]), "+f"(c[3])
        : "r"(a[0]), "r"(a[1]), "r"(a[2]), "r"(a[3]), "r"(b[0]), "r"(b[1]));
}

// ---------------------------------------------------------------------------
// Prep kernels: tf32-round x; transpose+round Wqkv and Wout to K-major
// ---------------------------------------------------------------------------
__global__ __launch_bounds__(256) void round_x(const float* __restrict__ x)
{
    int i = blockIdx.x * 256 + threadIdx.x;          // float4 index
    float4 v = ((const float4*)x)[i];
    v.x = to_tf32(v.x); v.y = to_tf32(v.y); v.z = to_tf32(v.z); v.w = to_tf32(v.w);
    ((float4*)g_xr)[i] = v;
}

__global__ __launch_bounds__(256) void transpose_wqkv(const float* __restrict__ W)
{
    __shared__ float t[32][33];
    const int tx = threadIdx.x & 31;
    const int ty = threadIdx.x >> 5;                  // 0..7
    const int f0 = blockIdx.x * 32;                   // 32 | 192 boundaries ok per-element
    const int e0 = blockIdx.y * 32;
    const int h = f0 / 192, fin = f0 % 192;
    const float* src = W + (size_t)h * EE * 192;
#pragma unroll
    for (int i = 0; i < 4; i++)
        t[ty + 8*i][tx] = src[(size_t)(e0 + ty + 8*i) * 192 + fin + tx];
    __syncthreads();
#pragma unroll
    for (int i = 0; i < 4; i++)
        g_wtq[(size_t)(f0 + ty + 8*i) * EE + e0 + tx] = to_tf32(t[tx][ty + 8*i]);
}

__global__ __launch_bounds__(256) void transpose_wout(const float* __restrict__ W)
{
    __shared__ float t[32][33];
    const int tx = threadIdx.x & 31;
    const int ty = threadIdx.x >> 5;
    const int n0 = blockIdx.x * 32;
    const int k0 = blockIdx.y * 32;
#pragma unroll
    for (int i = 0; i < 4; i++)
        t[ty + 8*i][tx] = W[(size_t)(k0 + ty + 8*i) * EE + n0 + tx];
    __syncthreads();
#pragma unroll
    for (int i = 0; i < 4; i++)
        g_wto[(size_t)(n0 + ty + 8*i) * EE + k0 + tx] = to_tf32(t[tx][ty + 8*i]);
}

// ---------------------------------------------------------------------------
// HMMA tf32 GEMM mainloop (device inline):
// CTA 128x128, 256 threads, 8 warps of 64x32. BK=32, cp.async double buffer.
// smem layout (floats): As[buf][row*36+k], Bs[buf][n*36+k]; stride 36 makes
// all fragment LDS.32 patterns conflict-free.
// acc[i][j][4]: m-tile i (16 rows), n-tile j (8 cols).
// ---------------------------------------------------------------------------
#define SM_AB_STRIDE 36
#define SM_STAGE (128*SM_AB_STRIDE)            // floats per stage per matrix
#define GEMM_SMEM (4*SM_STAGE*4)               // bytes: 2 matrices x 2 stages

__device__ __forceinline__ void hmma_mainloop(float* sm, uint32_t smu,
                                              const float* __restrict__ Ag,
                                              const float* __restrict__ Bg,
                                              float acc[4][4][4])
{
    const int tid = threadIdx.x;
    float* As = sm;                     // [2][SM_STAGE]
    float* Bs = sm + 2 * SM_STAGE;
    const uint32_t uA = smu;
    const uint32_t uB = smu + 2 * SM_STAGE * 4;

    const int lrow = tid >> 3;          // 0..31 -> with j loop covers 128 rows
    const int lc4  = tid & 7;           // float4 col within 32-float row chunk

    // issue one stage of cp.async
    auto issue = [&](int kt, int buf) {
#pragma unroll
        for (int j = 0; j < 4; j++) {
            int row = lrow + j * 32;
            uint32_t soff = (uint32_t)((buf * SM_STAGE + row * SM_AB_STRIDE + lc4 * 4) * 4);
            CP_ASYNC16(uA + soff, Ag + (size_t)row * EE + kt * 32 + lc4 * 4);
            CP_ASYNC16(uB + soff, Bg + (size_t)row * EE + kt * 32 + lc4 * 4);
        }
    };

    const int wid = tid >> 5;
    const int lane = tid & 31;
    const int qr = lane >> 2;           // 0..7
    const int qc = lane & 3;            // 0..3
    const int wr = (wid & 1) * 64;      // warp row base
    const int wc = (wid >> 1) * 32;     // warp col base

    issue(0, 0);
    CP_COMMIT();

    for (int kt = 0; kt < 32; kt++) {
        const int cur = kt & 1;
        if (kt < 31) {
            issue(kt + 1, cur ^ 1);
            CP_COMMIT();
            CP_WAIT1();
        } else {
            CP_WAIT0();
        }
        __syncthreads();

        const float* Ac = As + cur * SM_STAGE;
        const float* Bc = Bs + cur * SM_STAGE;

#pragma unroll
        for (int ks = 0; ks < 4; ks++) {
            const int k0 = ks * 8;
            uint32_t af[4][4], bf[4][2];
#pragma unroll
            for (int i = 0; i < 4; i++) {
                const float* p = Ac + (wr + i * 16 + qr) * SM_AB_STRIDE + k0 + qc;
                af[i][0] = __float_as_uint(p[0]);
                af[i][2] = __float_as_uint(p[4]);
                af[i][1] = __float_as_uint(p[8 * SM_AB_STRIDE]);
                af[i][3] = __float_as_uint(p[8 * SM_AB_STRIDE + 4]);
            }
#pragma unroll
            for (int j = 0; j < 4; j++) {
                const float* p = Bc + (wc + j * 8 + qr) * SM_AB_STRIDE + k0 + qc;
                bf[j][0] = __float_as_uint(p[0]);
                bf[j][1] = __float_as_uint(p[4]);
            }
#pragma unroll
            for (int i = 0; i < 4; i++)
#pragma unroll
                for (int j = 0; j < 4; j++)
                    mma_tf32_16n8k8(acc[i][j], af[i], bf[j]);
        }
        __syncthreads();
    }
}

// ---------------------------------------------------------------------------
// QKV GEMM (HMMA): C[128,128] of x @ WqkvT, + bias, scatter to g_k/g_q/g_v
// ---------------------------------------------------------------------------
__global__ __launch_bounds__(256, 2) void qkv_mma(const float* __restrict__ bqkv)
{
    extern __shared__ float sm[];
    const uint32_t smu = s2u(sm);

    const int c0 = blockIdx.x * 128;
    const int r0 = blockIdx.y * 128;

    float acc[4][4][4];
#pragma unroll
    for (int i = 0; i < 4; i++)
#pragma unroll
        for (int j = 0; j < 4; j++)
#pragma unroll
            for (int t = 0; t < 4; t++) acc[i][j][t] = 0.f;

    hmma_mainloop(sm, smu, g_xr + (size_t)r0 * EE, g_wtq + (size_t)c0 * EE, acc);

    const int wid = threadIdx.x >> 5;
    const int lane = threadIdx.x & 31;
    const int qr = lane >> 2, qc = lane & 3;
    const int wr = (wid & 1) * 64;
    const int wc = (wid >> 1) * 32;

#pragma unroll
    for (int i = 0; i < 4; i++) {
#pragma unroll
        for (int j = 0; j < 4; j++) {
            const int colF = c0 + wc + j * 8 + qc * 2;
            const int h = colF / 192, f = colF % 192;
            const int seg = f >> 6, fo = f & 63;
            float* dst = (seg == 0) ? g_k : (seg == 1) ? g_q : g_v;
            const float b0 = bqkv[colF], b1 = bqkv[colF + 1];
#pragma unroll
            for (int half = 0; half < 2; half++) {
                const int r = r0 + wr + i * 16 + qr + half * 8;
                const int bb = r >> 11;
                const int n_ = r & (NN - 1);
                size_t off = ((size_t)(bb * HH + h) * NN + n_) * HD + fo;
                float2 o;
                o.x = acc[i][j][half * 2 + 0] + b0;
                o.y = acc[i][j][half * 2 + 1] + b1;
                *(float2*)(dst + off) = o;
            }
        }
    }
}

// ---------------------------------------------------------------------------
// Output GEMM (HMMA): out = g_sa @ Wout + bout
// ---------------------------------------------------------------------------
__global__ __launch_bounds__(256, 2) void out_mma(const float* __restrict__ bout,
                                                  float* __restrict__ out)
{
    extern __shared__ float sm[];
    const uint32_t smu = s2u(sm);

    const int c0 = blockIdx.x * 128;
    const int r0 = blockIdx.y * 128;

    float acc[4][4][4];
#pragma unroll
    for (int i = 0; i < 4; i++)
#pragma unroll
        for (int j = 0; j < 4; j++)
#pragma unroll
            for (int t = 0; t < 4; t++) acc[i][j][t] = 0.f;

    hmma_mainloop(sm, smu, g_sa + (size_t)r0 * EE, g_wto + (size_t)c0 * EE, acc);

    const int wid = threadIdx.x >> 5;
    const int lane = threadIdx.x & 31;
    const int qr = lane >> 2, qc = lane & 3;
    const int wr = (wid & 1) * 64;
    const int wc = (wid >> 1) * 32;

#pragma unroll
    for (int i = 0; i < 4; i++) {
#pragma unroll
        for (int j = 0; j < 4; j++) {
            const int col = c0 + wc + j * 8 + qc * 2;
            const float b0 = bout[col], b1 = bout[col + 1];
#pragma unroll
            for (int half = 0; half < 2; half++) {
                const size_t r = (size_t)(r0 + wr + i * 16 + qr + half * 8);
                float2 o;
                o.x = acc[i][j][half * 2 + 0] + b0;
                o.y = acc[i][j][half * 2 + 1] + b1;
                *(float2*)(out + r * EE + col) = o;
            }
        }
    }
}

// ---------------------------------------------------------------------------
// Causal flash attention, fp32 (unchanged; epilogue tf32-rounds g_sa)
// ---------------------------------------------------------------------------
__global__ __launch_bounds__(128) void attn_kernel()
{
    extern __shared__ float smem[];
    float* Qs = smem;                 // [128][68]
    float* Ks = Qs + 128 * 68;        // [64][68]
    float* Vs = Ks + 64 * 68;         // [64][68]
    float* Ps = Vs + 64 * 68;         // [128][68]

    const int tid = threadIdx.x;
    const int ty  = tid >> 3;
    const int tx  = tid & 7;
    const int qt  = (int)gridDim.x - 1 - (int)blockIdx.x;
    const int bh  = blockIdx.y;

    const float* qptr = g_q + ((size_t)bh * NN + (size_t)qt * 128) * HD;
    const float* kptr = g_k + (size_t)bh * NN * HD;
    const float* vptr = g_v + (size_t)bh * NN * HD;

    const float scale = 0.125f;
#pragma unroll
    for (int i = 0; i < 16; i++) {
        int f = (tid + i * 128) * 4;
        int r = f >> 6, d = f & 63;
        float4 v = *(const float4*)(qptr + f);
        v.x *= scale; v.y *= scale; v.z *= scale; v.w *= scale;
        *(float4*)&Qs[r * 68 + d] = v;
    }

    float o[8][8];
    float m_run[8], l_run[8];
#pragma unroll
    for (int i = 0; i < 8; i++) {
        m_run[i] = -INFINITY;
        l_run[i] = 0.f;
#pragma unroll
        for (int d = 0; d < 8; d++) o[i][d] = 0.f;
    }

    const unsigned FULL = 0xffffffffu;
    const int jt_end = 2 * qt + 1;

    for (int jt = 0; jt <= jt_end; jt++) {
        __syncthreads();
#pragma unroll
        for (int i = 0; i < 8; i++) {
            int f = (tid + i * 128) * 4;
            int r = f >> 6, d = f & 63;
            *(float4*)&Ks[r * 68 + d] = *(const float4*)(kptr + (size_t)jt * 64 * HD + f);
            *(float4*)&Vs[r * 68 + d] = *(const float4*)(vptr + (size_t)jt * 64 * HD + f);
        }
        __syncthreads();

        float s[8][8];
#pragma unroll
        for (int i = 0; i < 8; i++)
#pragma unroll
            for (int jj = 0; jj < 8; jj++) s[i][jj] = 0.f;

#pragma unroll 4
        for (int dc = 0; dc < 16; dc++) {
            float4 a4[8];
#pragma unroll
            for (int i = 0; i < 8; i++)
                a4[i] = *(const float4*)&Qs[(ty + 16 * i) * 68 + dc * 4];
#pragma unroll
            for (int jj = 0; jj < 8; jj++) {
                float4 b4 = *(const float4*)&Ks[(tx + 8 * jj) * 68 + dc * 4];
#pragma unroll
                for (int i = 0; i < 8; i++)
                    s[i][jj] += a4[i].x * b4.x + a4[i].y * b4.y
                              + a4[i].z * b4.z + a4[i].w * b4.w;
            }
        }

        if (jt >= 2 * qt) {
#pragma unroll
            for (int i = 0; i < 8; i++) {
                int rg = qt * 128 + ty + 16 * i;
#pragma unroll
                for (int jj = 0; jj < 8; jj++) {
                    int jg = jt * 64 + tx + 8 * jj;
                    if (jg > rg) s[i][jj] = -INFINITY;
                }
            }
        }

#pragma unroll
        for (int i = 0; i < 8; i++) {
            float mt = s[i][0];
#pragma unroll
            for (int jj = 1; jj < 8; jj++) mt = fmaxf(mt, s[i][jj]);
            mt = fmaxf(mt, __shfl_xor_sync(FULL, mt, 1));
            mt = fmaxf(mt, __shfl_xor_sync(FULL, mt, 2));
            mt = fmaxf(mt, __shfl_xor_sync(FULL, mt, 4));

            float m_new = fmaxf(m_run[i], mt);
            float corr  = __expf(m_run[i] - m_new);

            float psum = 0.f;
#pragma unroll
            for (int jj = 0; jj < 8; jj++) {
                s[i][jj] = __expf(s[i][jj] - m_new);
                psum += s[i][jj];
            }
            psum += __shfl_xor_sync(FULL, psum, 1);
            psum += __shfl_xor_sync(FULL, psum, 2);
            psum += __shfl_xor_sync(FULL, psum, 4);

            l_run[i] = l_run[i] * corr + psum;
            m_run[i] = m_new;
#pragma unroll
            for (int d = 0; d < 8; d++) o[i][d] *= corr;
#pragma unroll
            for (int jj = 0; jj < 8; jj++)
                Ps[(ty + 16 * i) * 68 + tx + 8 * jj] = s[i][jj];
        }
        __syncthreads();

#pragma unroll 2
        for (int j = 0; j < 64; j++) {
            float vv[8];
#pragma unroll
            for (int d = 0; d < 8; d++)
                vv[d] = Vs[j * 68 + tx + 8 * d];
#pragma unroll
            for (int i = 0; i < 8; i++) {
                float pj = Ps[(ty + 16 * i) * 68 + j];
#pragma unroll
                for (int d = 0; d < 8; d++)
                    o[i][d] += pj * vv[d];
            }
        }
    }

    const int b = bh >> 4;
    const int h = bh & 15;
#pragma unroll
    for (int i = 0; i < 8; i++) {
        const float inv_l = 1.0f / l_run[i];
        const int qg = qt * 128 + ty + 16 * i;
        float* op = g_sa + ((size_t)b * NN + qg) * EE + h * HD;
#pragma unroll
        for (int d = 0; d < 8; d++)
            op[tx + 8 * d] = to_tf32(o[i][d] * inv_l);
    }
}

// ---------------------------------------------------------------------------
extern "C" void kernel_launch(void* const* d_in, const int* in_sizes, int n_in,
                              void* d_out, int out_size)
{
    const float* x    = (const float*)d_in[0];
    const float* Wqkv = (const float*)d_in[1];
    const float* bqkv = (const float*)d_in[2];
    const float* Wout = (const float*)d_in[3];
    const float* bout = (const float*)d_in[4];
    float* out = (float*)d_out;

    // 0) prep: round x, transpose+round weights to K-major
    round_x<<<ROWS * EE / 1024, 256>>>(x);
    transpose_wqkv<<<dim3(FF / 32, EE / 32), 256>>>(Wqkv);
    transpose_wout<<<dim3(EE / 32, EE / 32), 256>>>(Wout);

    // 1) QKV projection (HMMA tf32)
    cudaFuncSetAttribute(qkv_mma, cudaFuncAttributeMaxDynamicSharedMemorySize, GEMM_SMEM);
    qkv_mma<<<dim3(FF / 128, ROWS / 128), 256, GEMM_SMEM>>>(bqkv);

    // 2) Causal attention (fp32)
    {
        int smem_bytes = (128 + 64 + 64 + 128) * 68 * (int)sizeof(float);  // 104448
        cudaFuncSetAttribute(attn_kernel,
                             cudaFuncAttributeMaxDynamicSharedMemorySize, smem_bytes);
        dim3 grid(NN / 128, BB * HH);
        attn_kernel<<<grid, 128, smem_bytes>>>();
    }

    // 3) Output projection (HMMA tf32)
    cudaFuncSetAttribute(out_mma, cudaFuncAttributeMaxDynamicSharedMemorySize, GEMM_SMEM);
    out_mma<<<dim3(EE / 128, ROWS / 128), 256, GEMM_SMEM>>>(bout, out);
}

// round 11
// speedup vs baseline: 4.2425x; 1.9037x over previous
#include <cuda_runtime.h>
#include <math.h>
#include <stdint.h>

// Problem constants
#define BB 2
#define NN 2048
#define EE 1024
#define HH 16
#define HD 64
#define ROWS (BB*NN)          // 4096
#define FF (3*HH*HD)          // 3072

// Scratch (device globals; no allocations allowed)
__device__ float g_k[BB*HH*NN*HD];
__device__ float g_q[BB*HH*NN*HD];
__device__ float g_vt[BB*HH*HD*NN];    // V transposed: [bh][d][n]
__device__ float g_sa[BB*NN*EE];
__device__ float g_xr[ROWS*EE];        // x rounded to tf32
__device__ float g_wtq[FF*EE];         // Wqkv transposed [F][E], tf32-rounded
__device__ float g_wto[EE*EE];         // Wout transposed [n][k], tf32-rounded

// ---------------------------------------------------------------------------
// helpers
// ---------------------------------------------------------------------------
__device__ __forceinline__ float to_tf32(float x) {
    uint32_t u;
    asm("cvt.rna.tf32.f32 %0, %1;" : "=r"(u) : "f"(x));
    return __uint_as_float(u);
}
__device__ __forceinline__ uint32_t s2u(const void* p) {
    uint32_t a;
    asm("{ .reg .u64 t; cvta.to.shared.u64 t, %1; cvt.u32.u64 %0, t; }" : "=r"(a) : "l"(p));
    return a;
}

#define CP_ASYNC16(dst_u32, src_ptr) \
    asm volatile("cp.async.cg.shared.global [%0], [%1], 16;" :: "r"(dst_u32), "l"(src_ptr))
#define CP_COMMIT() asm volatile("cp.async.commit_group;" ::: "memory")
#define CP_WAIT1()  asm volatile("cp.async.wait_group 1;" ::: "memory")
#define CP_WAIT0()  asm volatile("cp.async.wait_group 0;" ::: "memory")

__device__ __forceinline__ void mma_tf32_16n8k8(float* c, const uint32_t* a, const uint32_t* b) {
    asm volatile(
        "mma.sync.aligned.m16n8k8.row.col.f32.tf32.tf32.f32 "
        "{%0,%1,%2,%3}, {%4,%5,%6,%7}, {%8,%9}, {%0,%1,%2,%3};"
        : "+f"(c[0]), "+f"(c[1]), "+f"(c[2]), "+f"(c[3])
        : "r"(a[0]), "r"(a[1]), "r"(a[2]), "r"(a[3]), "r"(b[0]), "r"(b[1]));
}

// ---------------------------------------------------------------------------
// Prep kernels: tf32-round x; transpose+round Wqkv and Wout to K-major
// ---------------------------------------------------------------------------
__global__ __launch_bounds__(256) void round_x(const float* __restrict__ x)
{
    int i = blockIdx.x * 256 + threadIdx.x;          // float4 index
    float4 v = ((const float4*)x)[i];
    v.x = to_tf32(v.x); v.y = to_tf32(v.y); v.z = to_tf32(v.z); v.w = to_tf32(v.w);
    ((float4*)g_xr)[i] = v;
}

__global__ __launch_bounds__(256) void transpose_wqkv(const float* __restrict__ W)
{
    __shared__ float t[32][33];
    const int tx = threadIdx.x & 31;
    const int ty = threadIdx.x >> 5;                  // 0..7
    const int f0 = blockIdx.x * 32;
    const int e0 = blockIdx.y * 32;
    const int h = f0 / 192, fin = f0 % 192;
    const float* src = W + (size_t)h * EE * 192;
#pragma unroll
    for (int i = 0; i < 4; i++)
        t[ty + 8*i][tx] = src[(size_t)(e0 + ty + 8*i) * 192 + fin + tx];
    __syncthreads();
#pragma unroll
    for (int i = 0; i < 4; i++)
        g_wtq[(size_t)(f0 + ty + 8*i) * EE + e0 + tx] = to_tf32(t[tx][ty + 8*i]);
}

__global__ __launch_bounds__(256) void transpose_wout(const float* __restrict__ W)
{
    __shared__ float t[32][33];
    const int tx = threadIdx.x & 31;
    const int ty = threadIdx.x >> 5;
    const int n0 = blockIdx.x * 32;
    const int k0 = blockIdx.y * 32;
#pragma unroll
    for (int i = 0; i < 4; i++)
        t[ty + 8*i][tx] = W[(size_t)(k0 + ty + 8*i) * EE + n0 + tx];
    __syncthreads();
#pragma unroll
    for (int i = 0; i < 4; i++)
        g_wto[(size_t)(n0 + ty + 8*i) * EE + k0 + tx] = to_tf32(t[tx][ty + 8*i]);
}

// ---------------------------------------------------------------------------
// HMMA tf32 GEMM mainloop: CTA 128x128, 256 threads, 8 warps of 64x32.
// BK=32, cp.async double buffer. smem stride 36 -> conflict-free fragments.
// ---------------------------------------------------------------------------
#define SM_AB_STRIDE 36
#define SM_STAGE (128*SM_AB_STRIDE)
#define GEMM_SMEM (4*SM_STAGE*4)

__device__ __forceinline__ void hmma_mainloop(float* sm, uint32_t smu,
                                              const float* __restrict__ Ag,
                                              const float* __restrict__ Bg,
                                              float acc[4][4][4])
{
    const int tid = threadIdx.x;
    float* As = sm;
    float* Bs = sm + 2 * SM_STAGE;
    const uint32_t uA = smu;
    const uint32_t uB = smu + 2 * SM_STAGE * 4;

    const int lrow = tid >> 3;
    const int lc4  = tid & 7;

    auto issue = [&](int kt, int buf) {
#pragma unroll
        for (int j = 0; j < 4; j++) {
            int row = lrow + j * 32;
            uint32_t soff = (uint32_t)((buf * SM_STAGE + row * SM_AB_STRIDE + lc4 * 4) * 4);
            CP_ASYNC16(uA + soff, Ag + (size_t)row * EE + kt * 32 + lc4 * 4);
            CP_ASYNC16(uB + soff, Bg + (size_t)row * EE + kt * 32 + lc4 * 4);
        }
    };

    const int wid = tid >> 5;
    const int lane = tid & 31;
    const int qr = lane >> 2;
    const int qc = lane & 3;
    const int wr = (wid & 1) * 64;
    const int wc = (wid >> 1) * 32;

    issue(0, 0);
    CP_COMMIT();

    for (int kt = 0; kt < 32; kt++) {
        const int cur = kt & 1;
        if (kt < 31) {
            issue(kt + 1, cur ^ 1);
            CP_COMMIT();
            CP_WAIT1();
        } else {
            CP_WAIT0();
        }
        __syncthreads();

        const float* Ac = As + cur * SM_STAGE;
        const float* Bc = Bs + cur * SM_STAGE;

#pragma unroll
        for (int ks = 0; ks < 4; ks++) {
            const int k0 = ks * 8;
            uint32_t af[4][4], bf[4][2];
#pragma unroll
            for (int i = 0; i < 4; i++) {
                const float* p = Ac + (wr + i * 16 + qr) * SM_AB_STRIDE + k0 + qc;
                af[i][0] = __float_as_uint(p[0]);
                af[i][2] = __float_as_uint(p[4]);
                af[i][1] = __float_as_uint(p[8 * SM_AB_STRIDE]);
                af[i][3] = __float_as_uint(p[8 * SM_AB_STRIDE + 4]);
            }
#pragma unroll
            for (int j = 0; j < 4; j++) {
                const float* p = Bc + (wc + j * 8 + qr) * SM_AB_STRIDE + k0 + qc;
                bf[j][0] = __float_as_uint(p[0]);
                bf[j][1] = __float_as_uint(p[4]);
            }
#pragma unroll
            for (int i = 0; i < 4; i++)
#pragma unroll
                for (int j = 0; j < 4; j++)
                    mma_tf32_16n8k8(acc[i][j], af[i], bf[j]);
        }
        __syncthreads();
    }
}

// ---------------------------------------------------------------------------
// QKV GEMM (HMMA): + bias, tf32-round, scatter: K->g_k, Q->g_q, V->g_vt (transposed)
// ---------------------------------------------------------------------------
__global__ __launch_bounds__(256, 2) void qkv_mma(const float* __restrict__ bqkv)
{
    extern __shared__ float sm[];
    const uint32_t smu = s2u(sm);

    const int c0 = blockIdx.x * 128;
    const int r0 = blockIdx.y * 128;

    float acc[4][4][4];
#pragma unroll
    for (int i = 0; i < 4; i++)
#pragma unroll
        for (int j = 0; j < 4; j++)
#pragma unroll
            for (int t = 0; t < 4; t++) acc[i][j][t] = 0.f;

    hmma_mainloop(sm, smu, g_xr + (size_t)r0 * EE, g_wtq + (size_t)c0 * EE, acc);

    const int wid = threadIdx.x >> 5;
    const int lane = threadIdx.x & 31;
    const int qr = lane >> 2, qc = lane & 3;
    const int wr = (wid & 1) * 64;
    const int wc = (wid >> 1) * 32;

#pragma unroll
    for (int i = 0; i < 4; i++) {
#pragma unroll
        for (int j = 0; j < 4; j++) {
            const int colF = c0 + wc + j * 8 + qc * 2;
            const int h = colF / 192, f = colF % 192;
            const int seg = f >> 6, fo = f & 63;
            const float b0 = bqkv[colF], b1 = bqkv[colF + 1];
#pragma unroll
            for (int half = 0; half < 2; half++) {
                const int r = r0 + wr + i * 16 + qr + half * 8;
                const int bb = r >> 11;
                const int n_ = r & (NN - 1);
                const float v0 = to_tf32(acc[i][j][half * 2 + 0] + b0);
                const float v1 = to_tf32(acc[i][j][half * 2 + 1] + b1);
                if (seg == 2) {
                    size_t vb = ((size_t)(bb * HH + h) * HD + fo) * NN + n_;
                    g_vt[vb] = v0;
                    g_vt[vb + NN] = v1;
                } else {
                    float* dst = (seg == 0) ? g_k : g_q;
                    size_t off = ((size_t)(bb * HH + h) * NN + n_) * HD + fo;
                    *(float2*)(dst + off) = make_float2(v0, v1);
                }
            }
        }
    }
}

// ---------------------------------------------------------------------------
// Output GEMM (HMMA): out = g_sa @ Wout + bout
// ---------------------------------------------------------------------------
__global__ __launch_bounds__(256, 2) void out_mma(const float* __restrict__ bout,
                                                  float* __restrict__ out)
{
    extern __shared__ float sm[];
    const uint32_t smu = s2u(sm);

    const int c0 = blockIdx.x * 128;
    const int r0 = blockIdx.y * 128;

    float acc[4][4][4];
#pragma unroll
    for (int i = 0; i < 4; i++)
#pragma unroll
        for (int j = 0; j < 4; j++)
#pragma unroll
            for (int t = 0; t < 4; t++) acc[i][j][t] = 0.f;

    hmma_mainloop(sm, smu, g_sa + (size_t)r0 * EE, g_wto + (size_t)c0 * EE, acc);

    const int wid = threadIdx.x >> 5;
    const int lane = threadIdx.x & 31;
    const int qr = lane >> 2, qc = lane & 3;
    const int wr = (wid & 1) * 64;
    const int wc = (wid >> 1) * 32;

#pragma unroll
    for (int i = 0; i < 4; i++) {
#pragma unroll
        for (int j = 0; j < 4; j++) {
            const int col = c0 + wc + j * 8 + qc * 2;
            const float b0 = bout[col], b1 = bout[col + 1];
#pragma unroll
            for (int half = 0; half < 2; half++) {
                const size_t r = (size_t)(r0 + wr + i * 16 + qr + half * 8);
                float2 o;
                o.x = acc[i][j][half * 2 + 0] + b0;
                o.y = acc[i][j][half * 2 + 1] + b1;
                *(float2*)(out + r * EE + col) = o;
            }
        }
    }
}

// ---------------------------------------------------------------------------
// Causal flash attention, HMMA tf32.
// CTA: 128 q-rows x (64-wide j-tiles), 256 threads, 8 warps x 16 rows.
// S = Q K^T and O += P V via m16n8k8 tf32. Softmax warp-local (quad shfl).
// K tile in smem [j][e], V pre-transposed in gmem -> smem [d][j].
// P round-trip through warp-private smem rows (syncwarp only).
// Stride 68 == 4 (mod 32): all fragment LDS patterns conflict-free.
// ---------------------------------------------------------------------------
#define ASW 68
#define ATT_SMEM ((4*64*ASW + 128*ASW)*4)   // 104448 bytes

__global__ __launch_bounds__(256, 2) void attn_mma()
{
    extern __shared__ float sm[];
    float* Ksm = sm;                    // [2][64*ASW]
    float* Vsm = sm + 2 * 64 * ASW;     // [2][64*ASW]  (V^T: [d][j])
    float* Psm = sm + 4 * 64 * ASW;     // [128*ASW]
    const uint32_t uK = s2u(sm);
    const uint32_t uV = uK + 2 * 64 * ASW * 4;

    const int tid  = threadIdx.x;
    const int wid  = tid >> 5, lane = tid & 31;
    const int qr   = lane >> 2, qc = lane & 3;
    const int qt   = (int)gridDim.x - 1 - (int)blockIdx.x;   // heavy first
    const int bh   = blockIdx.y;
    const int wr   = wid * 16;

    const float* kg = g_k  + (size_t)bh * NN * HD;
    const float* vg = g_vt + (size_t)bh * HD * NN;

    // Q fragments (g_q pre-rounded tf32; *0.125 exact power of 2)
    float qa[8][4];
    {
        const float* qb = g_q + ((size_t)bh * NN + qt * 128 + wr) * HD;
#pragma unroll
        for (int ks = 0; ks < 8; ks++) {
            qa[ks][0] = qb[qr * 64 + ks * 8 + qc] * 0.125f;
            qa[ks][1] = qb[(qr + 8) * 64 + ks * 8 + qc] * 0.125f;
            qa[ks][2] = qb[qr * 64 + ks * 8 + qc + 4] * 0.125f;
            qa[ks][3] = qb[(qr + 8) * 64 + ks * 8 + qc + 4] * 0.125f;
        }
    }

    float o[8][4];
#pragma unroll
    for (int nt = 0; nt < 8; nt++)
#pragma unroll
        for (int t = 0; t < 4; t++) o[nt][t] = 0.f;
    float m0 = -INFINITY, m1 = -INFINITY, l0 = 0.f, l1 = 0.f;

    const unsigned FULL = 0xffffffffu;
    const int jt_end = 2 * qt + 1;

    // cp.async one (K,V) stage: 64 rows x 64 floats each
    auto issue = [&](int jt) {
        const int buf = jt & 1;
#pragma unroll
        for (int i = 0; i < 4; i++) {
            int idx = tid + i * 256;            // 0..1023
            int row = idx >> 4;
            int c4  = (idx & 15) * 4;
            uint32_t soff = (uint32_t)((buf * 64 * ASW + row * ASW + c4) * 4);
            CP_ASYNC16(uK + soff, kg + (size_t)(jt * 64 + row) * HD + c4);
            CP_ASYNC16(uV + soff, vg + (size_t)row * NN + jt * 64 + c4);
        }
        CP_COMMIT();
    };

    issue(0);

    for (int jt = 0; jt <= jt_end; jt++) {
        if (jt < jt_end) { issue(jt + 1); CP_WAIT1(); } else { CP_WAIT0(); }
        __syncthreads();

        const float* Kc = Ksm + (jt & 1) * 64 * ASW;
        const float* Vc = Vsm + (jt & 1) * 64 * ASW;

        // warp fully masked for this j-tile? (rows all < min col)
        const bool active = (jt * 64 <= qt * 128 + wr + 15);
        if (active) {
            // ---- S = Q K^T ----
            float s[8][4];
#pragma unroll
            for (int nt = 0; nt < 8; nt++)
#pragma unroll
                for (int t = 0; t < 4; t++) s[nt][t] = 0.f;

#pragma unroll
            for (int ks = 0; ks < 8; ks++) {
                const int k0 = ks * 8;
#pragma unroll
                for (int nt = 0; nt < 8; nt++) {
                    uint32_t bf[2];
                    const float* p = Kc + (nt * 8 + qr) * ASW + k0 + qc;
                    bf[0] = __float_as_uint(p[0]);
                    bf[1] = __float_as_uint(p[4]);
                    mma_tf32_16n8k8(s[nt], (const uint32_t*)qa[ks], bf);
                }
            }

            // ---- causal mask (only tiles straddling diagonal) ----
            if (jt >= 2 * qt) {
                const int rg0 = qt * 128 + wr + qr;
                const int rg1 = rg0 + 8;
#pragma unroll
                for (int nt = 0; nt < 8; nt++) {
                    const int jg = jt * 64 + nt * 8 + 2 * qc;
                    if (jg > rg0)     s[nt][0] = -INFINITY;
                    if (jg + 1 > rg0) s[nt][1] = -INFINITY;
                    if (jg > rg1)     s[nt][2] = -INFINITY;
                    if (jg + 1 > rg1) s[nt][3] = -INFINITY;
                }
            }

            // ---- online softmax (rows qr / qr+8; quad shfl) ----
            float mt0 = s[0][0], mt1 = s[0][2];
#pragma unroll
            for (int nt = 0; nt < 8; nt++) {
                mt0 = fmaxf(mt0, fmaxf(s[nt][0], s[nt][1]));
                mt1 = fmaxf(mt1, fmaxf(s[nt][2], s[nt][3]));
            }
            mt0 = fmaxf(mt0, __shfl_xor_sync(FULL, mt0, 1));
            mt0 = fmaxf(mt0, __shfl_xor_sync(FULL, mt0, 2));
            mt1 = fmaxf(mt1, __shfl_xor_sync(FULL, mt1, 1));
            mt1 = fmaxf(mt1, __shfl_xor_sync(FULL, mt1, 2));

            const float mn0 = fmaxf(m0, mt0);
            const float mn1 = fmaxf(m1, mt1);
            const float c0_ = __expf(m0 - mn0);
            const float c1_ = __expf(m1 - mn1);

            float ps0 = 0.f, ps1 = 0.f;
#pragma unroll
            for (int nt = 0; nt < 8; nt++) {
                s[nt][0] = __expf(s[nt][0] - mn0);
                s[nt][1] = __expf(s[nt][1] - mn0);
                s[nt][2] = __expf(s[nt][2] - mn1);
                s[nt][3] = __expf(s[nt][3] - mn1);
                ps0 += s[nt][0] + s[nt][1];
                ps1 += s[nt][2] + s[nt][3];
            }
            ps0 += __shfl_xor_sync(FULL, ps0, 1);
            ps0 += __shfl_xor_sync(FULL, ps0, 2);
            ps1 += __shfl_xor_sync(FULL, ps1, 1);
            ps1 += __shfl_xor_sync(FULL, ps1, 2);

            l0 = l0 * c0_ + ps0;  m0 = mn0;
            l1 = l1 * c1_ + ps1;  m1 = mn1;
#pragma unroll
            for (int nt = 0; nt < 8; nt++) {
                o[nt][0] *= c0_;  o[nt][1] *= c0_;
                o[nt][2] *= c1_;  o[nt][3] *= c1_;
            }

            // ---- write P to warp-private smem rows (tf32-rounded) ----
#pragma unroll
            for (int nt = 0; nt < 8; nt++) {
                *(float2*)&Psm[(wr + qr) * ASW + nt * 8 + 2 * qc] =
                    make_float2(to_tf32(s[nt][0]), to_tf32(s[nt][1]));
                *(float2*)&Psm[(wr + qr + 8) * ASW + nt * 8 + 2 * qc] =
                    make_float2(to_tf32(s[nt][2]), to_tf32(s[nt][3]));
            }
            __syncwarp();

            // ---- O += P V  (A from Psm, B from V^T tile) ----
#pragma unroll
            for (int ks = 0; ks < 8; ks++) {
                const int k0 = ks * 8;
                uint32_t af[4];
                af[0] = __float_as_uint(Psm[(wr + qr) * ASW + k0 + qc]);
                af[1] = __float_as_uint(Psm[(wr + qr + 8) * ASW + k0 + qc]);
                af[2] = __float_as_uint(Psm[(wr + qr) * ASW + k0 + qc + 4]);
                af[3] = __float_as_uint(Psm[(wr + qr + 8) * ASW + k0 + qc + 4]);
#pragma unroll
                for (int nt = 0; nt < 8; nt++) {
                    uint32_t bf[2];
                    const float* p = Vc + (nt * 8 + qr) * ASW + k0 + qc;
                    bf[0] = __float_as_uint(p[0]);
                    bf[1] = __float_as_uint(p[4]);
                    mma_tf32_16n8k8(o[nt], af, bf);
                }
            }
        }
        __syncthreads();
    }

    // ---- epilogue: normalize + scatter to g_sa [B, N, E] (tf32-rounded) ----
    const float il0 = 1.0f / l0;
    const float il1 = 1.0f / l1;
    const int b = bh >> 4;
    const int h = bh & 15;
    const int n0 = qt * 128 + wr + qr;
    float* o0 = g_sa + ((size_t)b * NN + n0) * EE + h * HD;
    float* o1 = o0 + (size_t)8 * EE;
#pragma unroll
    for (int nt = 0; nt < 8; nt++) {
        const int d = nt * 8 + 2 * qc;
        *(float2*)(o0 + d) = make_float2(to_tf32(o[nt][0] * il0), to_tf32(o[nt][1] * il0));
        *(float2*)(o1 + d) = make_float2(to_tf32(o[nt][2] * il1), to_tf32(o[nt][3] * il1));
    }
}

// ---------------------------------------------------------------------------
extern "C" void kernel_launch(void* const* d_in, const int* in_sizes, int n_in,
                              void* d_out, int out_size)
{
    const float* x    = (const float*)d_in[0];
    const float* Wqkv = (const float*)d_in[1];
    const float* bqkv = (const float*)d_in[2];
    const float* Wout = (const float*)d_in[3];
    const float* bout = (const float*)d_in[4];
    float* out = (float*)d_out;

    // 0) prep: round x, transpose+round weights to K-major
    round_x<<<ROWS * EE / 1024, 256>>>(x);
    transpose_wqkv<<<dim3(FF / 32, EE / 32), 256>>>(Wqkv);
    transpose_wout<<<dim3(EE / 32, EE / 32), 256>>>(Wout);

    // 1) QKV projection (HMMA tf32)
    cudaFuncSetAttribute(qkv_mma, cudaFuncAttributeMaxDynamicSharedMemorySize, GEMM_SMEM);
    qkv_mma<<<dim3(FF / 128, ROWS / 128), 256, GEMM_SMEM>>>(bqkv);

    // 2) Causal attention (HMMA tf32)
    cudaFuncSetAttribute(attn_mma, cudaFuncAttributeMaxDynamicSharedMemorySize, ATT_SMEM);
    attn_mma<<<dim3(NN / 128, BB * HH), 256, ATT_SMEM>>>();

    // 3) Output projection (HMMA tf32)
    cudaFuncSetAttribute(out_mma, cudaFuncAttributeMaxDynamicSharedMemorySize, GEMM_SMEM);
    out_mma<<<dim3(EE / 128, ROWS / 128), 256, GEMM_SMEM>>>(bout, out);
}

// round 12
// speedup vs baseline: 4.3238x; 1.0192x over previous
#include <cuda_runtime.h>
#include <math.h>
#include <stdint.h>

// Problem constants
#define BB 2
#define NN 2048
#define EE 1024
#define HH 16
#define HD 64
#define ROWS (BB*NN)          // 4096
#define FF (3*HH*HD)          // 3072

// Scratch (device globals; no allocations allowed)
__device__ float g_k[BB*HH*NN*HD];
__device__ float g_q[BB*HH*NN*HD];
__device__ float g_vt[BB*HH*HD*NN];    // V transposed: [bh][d][n]
__device__ float g_sa[BB*NN*EE];
__device__ float g_xr[ROWS*EE];        // x rounded to tf32
__device__ float g_wtq[FF*EE];         // Wqkv transposed [F][E], tf32-rounded
__device__ float g_wto[EE*EE];         // Wout transposed [n][k], tf32-rounded

// ---------------------------------------------------------------------------
// helpers
// ---------------------------------------------------------------------------
__device__ __forceinline__ float to_tf32(float x) {
    uint32_t u;
    asm("cvt.rna.tf32.f32 %0, %1;" : "=r"(u) : "f"(x));
    return __uint_as_float(u);
}
__device__ __forceinline__ uint32_t s2u(const void* p) {
    uint32_t a;
    asm("{ .reg .u64 t; cvta.to.shared.u64 t, %1; cvt.u32.u64 %0, t; }" : "=r"(a) : "l"(p));
    return a;
}

#define CP_ASYNC16(dst_u32, src_ptr) \
    asm volatile("cp.async.cg.shared.global [%0], [%1], 16;" :: "r"(dst_u32), "l"(src_ptr))
#define CP_COMMIT() asm volatile("cp.async.commit_group;" ::: "memory")
#define CP_WAIT0()  asm volatile("cp.async.wait_group 0;" ::: "memory")

__device__ __forceinline__ void mma_tf32_16n8k8(float* c, const uint32_t* a, const uint32_t* b) {
    asm volatile(
        "mma.sync.aligned.m16n8k8.row.col.f32.tf32.tf32.f32 "
        "{%0,%1,%2,%3}, {%4,%5,%6,%7}, {%8,%9}, {%0,%1,%2,%3};"
        : "+f"(c[0]), "+f"(c[1]), "+f"(c[2]), "+f"(c[3])
        : "r"(a[0]), "r"(a[1]), "r"(a[2]), "r"(a[3]), "r"(b[0]), "r"(b[1]));
}

// ---------------------------------------------------------------------------
// Fused prep kernel: round x (blocks [0,4096)); transpose+round Wqkv
// (blocks [4096,7168)); transpose+round Wout (blocks [7168,8192)).
// ---------------------------------------------------------------------------
__global__ __launch_bounds__(256) void prep(const float* __restrict__ x,
                                            const float* __restrict__ Wq,
                                            const float* __restrict__ Wo)
{
    __shared__ float t[32][33];
    const int b = blockIdx.x;
    const int tid = threadIdx.x;

    if (b < 4096) {
        int i = b * 256 + tid;
        float4 v = ((const float4*)x)[i];
        v.x = to_tf32(v.x); v.y = to_tf32(v.y); v.z = to_tf32(v.z); v.w = to_tf32(v.w);
        ((float4*)g_xr)[i] = v;
        return;
    }

    const int tx = tid & 31;
    const int ty = tid >> 5;

    if (b < 7168) {
        const int bb = b - 4096;
        const int f0 = (bb % 96) * 32;
        const int e0 = (bb / 96) * 32;
        const int h = f0 / 192, fin = f0 % 192;
        const float* src = Wq + (size_t)h * EE * 192;
#pragma unroll
        for (int i = 0; i < 4; i++)
            t[ty + 8*i][tx] = src[(size_t)(e0 + ty + 8*i) * 192 + fin + tx];
        __syncthreads();
#pragma unroll
        for (int i = 0; i < 4; i++)
            g_wtq[(size_t)(f0 + ty + 8*i) * EE + e0 + tx] = to_tf32(t[tx][ty + 8*i]);
    } else {
        const int bb = b - 7168;
        const int n0 = (bb % 32) * 32;
        const int k0 = (bb / 32) * 32;
#pragma unroll
        for (int i = 0; i < 4; i++)
            t[ty + 8*i][tx] = Wo[(size_t)(k0 + ty + 8*i) * EE + n0 + tx];
        __syncthreads();
#pragma unroll
        for (int i = 0; i < 4; i++)
            g_wto[(size_t)(n0 + ty + 8*i) * EE + k0 + tx] = to_tf32(t[tx][ty + 8*i]);
    }
}

// ---------------------------------------------------------------------------
// HMMA tf32 GEMM mainloop: CTA 128x128, 256 threads, 8 warps of 64x32.
// BK=32, cp.async double buffer, ONE __syncthreads per k-iter.
// smem stride 36 -> conflict-free fragments.
// ---------------------------------------------------------------------------
#define SM_AB_STRIDE 36
#define SM_STAGE (128*SM_AB_STRIDE)
#define GEMM_SMEM (4*SM_STAGE*4)

__device__ __forceinline__ void hmma_mainloop(float* sm, uint32_t smu,
                                              const float* __restrict__ Ag,
                                              const float* __restrict__ Bg,
                                              float acc[4][4][4])
{
    const int tid = threadIdx.x;
    float* As = sm;
    float* Bs = sm + 2 * SM_STAGE;
    const uint32_t uA = smu;
    const uint32_t uB = smu + 2 * SM_STAGE * 4;

    const int lrow = tid >> 3;
    const int lc4  = tid & 7;

    auto issue = [&](int kt, int buf) {
#pragma unroll
        for (int j = 0; j < 4; j++) {
            int row = lrow + j * 32;
            uint32_t soff = (uint32_t)((buf * SM_STAGE + row * SM_AB_STRIDE + lc4 * 4) * 4);
            CP_ASYNC16(uA + soff, Ag + (size_t)row * EE + kt * 32 + lc4 * 4);
            CP_ASYNC16(uB + soff, Bg + (size_t)row * EE + kt * 32 + lc4 * 4);
        }
    };

    const int wid = tid >> 5;
    const int lane = tid & 31;
    const int qr = lane >> 2;
    const int qc = lane & 3;
    const int wr = (wid & 1) * 64;
    const int wc = (wid >> 1) * 32;

    issue(0, 0);
    CP_COMMIT();

#pragma unroll 1
    for (int kt = 0; kt < 32; kt++) {
        const int cur = kt & 1;
        CP_WAIT0();
        __syncthreads();
        // safe: all warps are past compute of kt-1, which read buffer cur^1
        if (kt < 31) { issue(kt + 1, cur ^ 1); CP_COMMIT(); }

        const float* Ac = As + cur * SM_STAGE;
        const float* Bc = Bs + cur * SM_STAGE;

#pragma unroll
        for (int ks = 0; ks < 4; ks++) {
            const int k0 = ks * 8;
            uint32_t af[4][4], bf[4][2];
#pragma unroll
            for (int i = 0; i < 4; i++) {
                const float* p = Ac + (wr + i * 16 + qr) * SM_AB_STRIDE + k0 + qc;
                af[i][0] = __float_as_uint(p[0]);
                af[i][2] = __float_as_uint(p[4]);
                af[i][1] = __float_as_uint(p[8 * SM_AB_STRIDE]);
                af[i][3] = __float_as_uint(p[8 * SM_AB_STRIDE + 4]);
            }
#pragma unroll
            for (int j = 0; j < 4; j++) {
                const float* p = Bc + (wc + j * 8 + qr) * SM_AB_STRIDE + k0 + qc;
                bf[j][0] = __float_as_uint(p[0]);
                bf[j][1] = __float_as_uint(p[4]);
            }
#pragma unroll
            for (int i = 0; i < 4; i++)
#pragma unroll
                for (int j = 0; j < 4; j++)
                    mma_tf32_16n8k8(acc[i][j], af[i], bf[j]);
        }
    }
}

// ---------------------------------------------------------------------------
// QKV GEMM (HMMA): + bias, tf32-round, scatter: K->g_k, Q->g_q, V->g_vt (transposed)
// ---------------------------------------------------------------------------
__global__ __launch_bounds__(256, 2) void qkv_mma(const float* __restrict__ bqkv)
{
    extern __shared__ float sm[];
    const uint32_t smu = s2u(sm);

    const int c0 = blockIdx.x * 128;
    const int r0 = blockIdx.y * 128;

    float acc[4][4][4];
#pragma unroll
    for (int i = 0; i < 4; i++)
#pragma unroll
        for (int j = 0; j < 4; j++)
#pragma unroll
            for (int t = 0; t < 4; t++) acc[i][j][t] = 0.f;

    hmma_mainloop(sm, smu, g_xr + (size_t)r0 * EE, g_wtq + (size_t)c0 * EE, acc);

    const int wid = threadIdx.x >> 5;
    const int lane = threadIdx.x & 31;
    const int qr = lane >> 2, qc = lane & 3;
    const int wr = (wid & 1) * 64;
    const int wc = (wid >> 1) * 32;

#pragma unroll
    for (int i = 0; i < 4; i++) {
#pragma unroll
        for (int j = 0; j < 4; j++) {
            const int colF = c0 + wc + j * 8 + qc * 2;
            const int h = colF / 192, f = colF % 192;
            const int seg = f >> 6, fo = f & 63;
            const float b0 = bqkv[colF], b1 = bqkv[colF + 1];
#pragma unroll
            for (int half = 0; half < 2; half++) {
                const int r = r0 + wr + i * 16 + qr + half * 8;
                const int bb = r >> 11;
                const int n_ = r & (NN - 1);
                const float v0 = to_tf32(acc[i][j][half * 2 + 0] + b0);
                const float v1 = to_tf32(acc[i][j][half * 2 + 1] + b1);
                if (seg == 2) {
                    size_t vb = ((size_t)(bb * HH + h) * HD + fo) * NN + n_;
                    g_vt[vb] = v0;
                    g_vt[vb + NN] = v1;
                } else {
                    float* dst = (seg == 0) ? g_k : g_q;
                    size_t off = ((size_t)(bb * HH + h) * NN + n_) * HD + fo;
                    *(float2*)(dst + off) = make_float2(v0, v1);
                }
            }
        }
    }
}

// ---------------------------------------------------------------------------
// Output GEMM (HMMA): out = g_sa @ Wout + bout
// ---------------------------------------------------------------------------
__global__ __launch_bounds__(256, 2) void out_mma(const float* __restrict__ bout,
                                                  float* __restrict__ out)
{
    extern __shared__ float sm[];
    const uint32_t smu = s2u(sm);

    const int c0 = blockIdx.x * 128;
    const int r0 = blockIdx.y * 128;

    float acc[4][4][4];
#pragma unroll
    for (int i = 0; i < 4; i++)
#pragma unroll
        for (int j = 0; j < 4; j++)
#pragma unroll
            for (int t = 0; t < 4; t++) acc[i][j][t] = 0.f;

    hmma_mainloop(sm, smu, g_sa + (size_t)r0 * EE, g_wto + (size_t)c0 * EE, acc);

    const int wid = threadIdx.x >> 5;
    const int lane = threadIdx.x & 31;
    const int qr = lane >> 2, qc = lane & 3;
    const int wr = (wid & 1) * 64;
    const int wc = (wid >> 1) * 32;

#pragma unroll
    for (int i = 0; i < 4; i++) {
#pragma unroll
        for (int j = 0; j < 4; j++) {
            const int col = c0 + wc + j * 8 + qc * 2;
            const float b0 = bout[col], b1 = bout[col + 1];
#pragma unroll
            for (int half = 0; half < 2; half++) {
                const size_t r = (size_t)(r0 + wr + i * 16 + qr + half * 8);
                float2 o;
                o.x = acc[i][j][half * 2 + 0] + b0;
                o.y = acc[i][j][half * 2 + 1] + b1;
                *(float2*)(out + r * EE + col) = o;
            }
        }
    }
}

// ---------------------------------------------------------------------------
// Causal flash attention, HMMA tf32, no online-max (scores are O(10); fp32
// exp safe without stabilization), one __syncthreads per j-tile.
// CTA: 128 q-rows, 256 threads, 8 warps x 16 rows. K smem [j][e], V^T smem [d][j].
// ---------------------------------------------------------------------------
#define ASW 68
#define ATT_SMEM ((4*64*ASW + 128*ASW)*4)   // 104448 bytes

__global__ __launch_bounds__(256, 2) void attn_mma()
{
    extern __shared__ float sm[];
    float* Ksm = sm;                    // [2][64*ASW]
    float* Vsm = sm + 2 * 64 * ASW;     // [2][64*ASW]  (V^T: [d][j])
    float* Psm = sm + 4 * 64 * ASW;     // [128*ASW]
    const uint32_t uK = s2u(sm);
    const uint32_t uV = uK + 2 * 64 * ASW * 4;

    const int tid  = threadIdx.x;
    const int wid  = tid >> 5, lane = tid & 31;
    const int qr   = lane >> 2, qc = lane & 3;
    const int qt   = (int)gridDim.x - 1 - (int)blockIdx.x;   // heavy first
    const int bh   = blockIdx.y;
    const int wr   = wid * 16;

    const float* kg = g_k  + (size_t)bh * NN * HD;
    const float* vg = g_vt + (size_t)bh * HD * NN;

    // Q fragments (g_q pre-rounded tf32; *0.125 exact power of 2)
    float qa[8][4];
    {
        const float* qb = g_q + ((size_t)bh * NN + qt * 128 + wr) * HD;
#pragma unroll
        for (int ks = 0; ks < 8; ks++) {
            qa[ks][0] = qb[qr * 64 + ks * 8 + qc] * 0.125f;
            qa[ks][1] = qb[(qr + 8) * 64 + ks * 8 + qc] * 0.125f;
            qa[ks][2] = qb[qr * 64 + ks * 8 + qc + 4] * 0.125f;
            qa[ks][3] = qb[(qr + 8) * 64 + ks * 8 + qc + 4] * 0.125f;
        }
    }

    float o[8][4];
#pragma unroll
    for (int nt = 0; nt < 8; nt++)
#pragma unroll
        for (int t = 0; t < 4; t++) o[nt][t] = 0.f;
    float l0 = 0.f, l1 = 0.f;

    const unsigned FULL = 0xffffffffu;
    const int jt_end = 2 * qt + 1;

    // cp.async one (K,V) stage: 64 rows x 64 floats each
    auto issue = [&](int jt) {
        const int buf = jt & 1;
#pragma unroll
        for (int i = 0; i < 4; i++) {
            int idx = tid + i * 256;            // 0..1023
            int row = idx >> 4;
            int c4  = (idx & 15) * 4;
            uint32_t soff = (uint32_t)((buf * 64 * ASW + row * ASW + c4) * 4);
            CP_ASYNC16(uK + soff, kg + (size_t)(jt * 64 + row) * HD + c4);
            CP_ASYNC16(uV + soff, vg + (size_t)row * NN + jt * 64 + c4);
        }
        CP_COMMIT();
    };

    issue(0);

#pragma unroll 1
    for (int jt = 0; jt <= jt_end; jt++) {
        CP_WAIT0();
        __syncthreads();
        // safe: all warps finished compute jt-1 (read buf (jt+1)&1)
        if (jt < jt_end) issue(jt + 1);

        const float* Kc = Ksm + (jt & 1) * 64 * ASW;
        const float* Vc = Vsm + (jt & 1) * 64 * ASW;

        const bool active = (jt * 64 <= qt * 128 + wr + 15);
        if (active) {
            // ---- S = Q K^T ----
            float s[8][4];
#pragma unroll
            for (int nt = 0; nt < 8; nt++)
#pragma unroll
                for (int t = 0; t < 4; t++) s[nt][t] = 0.f;

#pragma unroll
            for (int ks = 0; ks < 8; ks++) {
                const int k0 = ks * 8;
#pragma unroll
                for (int nt = 0; nt < 8; nt++) {
                    uint32_t bf[2];
                    const float* p = Kc + (nt * 8 + qr) * ASW + k0 + qc;
                    bf[0] = __float_as_uint(p[0]);
                    bf[1] = __float_as_uint(p[4]);
                    mma_tf32_16n8k8(s[nt], (const uint32_t*)qa[ks], bf);
                }
            }

            // ---- causal mask (tiles straddling diagonal) ----
            if (jt >= 2 * qt) {
                const int rg0 = qt * 128 + wr + qr;
                const int rg1 = rg0 + 8;
#pragma unroll
                for (int nt = 0; nt < 8; nt++) {
                    const int jg = jt * 64 + nt * 8 + 2 * qc;
                    if (jg > rg0)     s[nt][0] = -INFINITY;
                    if (jg + 1 > rg0) s[nt][1] = -INFINITY;
                    if (jg > rg1)     s[nt][2] = -INFINITY;
                    if (jg + 1 > rg1) s[nt][3] = -INFINITY;
                }
            }

            // ---- softmax numerator (no max-shift; scores bounded) ----
            float ps0 = 0.f, ps1 = 0.f;
#pragma unroll
            for (int nt = 0; nt < 8; nt++) {
                s[nt][0] = __expf(s[nt][0]);
                s[nt][1] = __expf(s[nt][1]);
                s[nt][2] = __expf(s[nt][2]);
                s[nt][3] = __expf(s[nt][3]);
                ps0 += s[nt][0] + s[nt][1];
                ps1 += s[nt][2] + s[nt][3];
            }
            ps0 += __shfl_xor_sync(FULL, ps0, 1);
            ps0 += __shfl_xor_sync(FULL, ps0, 2);
            ps1 += __shfl_xor_sync(FULL, ps1, 1);
            ps1 += __shfl_xor_sync(FULL, ps1, 2);
            l0 += ps0;
            l1 += ps1;

            // ---- write P to warp-private smem rows (tf32-rounded) ----
#pragma unroll
            for (int nt = 0; nt < 8; nt++) {
                *(float2*)&Psm[(wr + qr) * ASW + nt * 8 + 2 * qc] =
                    make_float2(to_tf32(s[nt][0]), to_tf32(s[nt][1]));
                *(float2*)&Psm[(wr + qr + 8) * ASW + nt * 8 + 2 * qc] =
                    make_float2(to_tf32(s[nt][2]), to_tf32(s[nt][3]));
            }
            __syncwarp();

            // ---- O += P V  (A from Psm, B from V^T tile) ----
#pragma unroll
            for (int ks = 0; ks < 8; ks++) {
                const int k0 = ks * 8;
                uint32_t af[4];
                af[0] = __float_as_uint(Psm[(wr + qr) * ASW + k0 + qc]);
                af[1] = __float_as_uint(Psm[(wr + qr + 8) * ASW + k0 + qc]);
                af[2] = __float_as_uint(Psm[(wr + qr) * ASW + k0 + qc + 4]);
                af[3] = __float_as_uint(Psm[(wr + qr + 8) * ASW + k0 + qc + 4]);
#pragma unroll
                for (int nt = 0; nt < 8; nt++) {
                    uint32_t bf[2];
                    const float* p = Vc + (nt * 8 + qr) * ASW + k0 + qc;
                    bf[0] = __float_as_uint(p[0]);
                    bf[1] = __float_as_uint(p[4]);
                    mma_tf32_16n8k8(o[nt], af, bf);
                }
            }
        }
    }

    // ---- epilogue: normalize + scatter to g_sa [B, N, E] (tf32-rounded) ----
    const float il0 = 1.0f / l0;
    const float il1 = 1.0f / l1;
    const int b = bh >> 4;
    const int h = bh & 15;
    const int n0 = qt * 128 + wr + qr;
    float* o0 = g_sa + ((size_t)b * NN + n0) * EE + h * HD;
    float* o1 = o0 + (size_t)8 * EE;
#pragma unroll
    for (int nt = 0; nt < 8; nt++) {
        const int d = nt * 8 + 2 * qc;
        *(float2*)(o0 + d) = make_float2(to_tf32(o[nt][0] * il0), to_tf32(o[nt][1] * il0));
        *(float2*)(o1 + d) = make_float2(to_tf32(o[nt][2] * il1), to_tf32(o[nt][3] * il1));
    }
}

// ---------------------------------------------------------------------------
extern "C" void kernel_launch(void* const* d_in, const int* in_sizes, int n_in,
                              void* d_out, int out_size)
{
    const float* x    = (const float*)d_in[0];
    const float* Wqkv = (const float*)d_in[1];
    const float* bqkv = (const float*)d_in[2];
    const float* Wout = (const float*)d_in[3];
    const float* bout = (const float*)d_in[4];
    float* out = (float*)d_out;

    // 0) fused prep: round x, transpose+round weights
    prep<<<8192, 256>>>(x, Wqkv, Wout);

    // 1) QKV projection (HMMA tf32)
    cudaFuncSetAttribute(qkv_mma, cudaFuncAttributeMaxDynamicSharedMemorySize, GEMM_SMEM);
    qkv_mma<<<dim3(FF / 128, ROWS / 128), 256, GEMM_SMEM>>>(bqkv);

    // 2) Causal attention (HMMA tf32)
    cudaFuncSetAttribute(attn_mma, cudaFuncAttributeMaxDynamicSharedMemorySize, ATT_SMEM);
    attn_mma<<<dim3(NN / 128, BB * HH), 256, ATT_SMEM>>>();

    // 3) Output projection (HMMA tf32)
    cudaFuncSetAttribute(out_mma, cudaFuncAttributeMaxDynamicSharedMemorySize, GEMM_SMEM);
    out_mma<<<dim3(EE / 128, ROWS / 128), 256, GEMM_SMEM>>>(bout, out);
}

// round 13
// speedup vs baseline: 4.7902x; 1.1079x over previous
#include <cuda_runtime.h>
#include <math.h>
#include <stdint.h>

// Problem constants
#define BB 2
#define NN 2048
#define EE 1024
#define HH 16
#define HD 64
#define ROWS (BB*NN)          // 4096
#define FF (3*HH*HD)          // 3072

// Scratch (device globals; no allocations allowed)
__device__ float g_k[BB*HH*NN*HD];
__device__ float g_q[BB*HH*NN*HD];
__device__ float g_vt[BB*HH*HD*NN];    // V transposed: [bh][d][n]
__device__ float g_sa[BB*NN*EE];
__device__ float g_xr[ROWS*EE];        // x rounded to tf32
__device__ float g_wtq[FF*EE];         // Wqkv transposed [F][E], tf32-rounded
__device__ float g_wto[EE*EE];         // Wout transposed [n][k], tf32-rounded

// ---------------------------------------------------------------------------
// helpers
// ---------------------------------------------------------------------------
__device__ __forceinline__ float to_tf32(float x) {
    uint32_t u;
    asm("cvt.rna.tf32.f32 %0, %1;" : "=r"(u) : "f"(x));
    return __uint_as_float(u);
}
__device__ __forceinline__ uint32_t s2u(const void* p) {
    uint32_t a;
    asm("{ .reg .u64 t; cvta.to.shared.u64 t, %1; cvt.u32.u64 %0, t; }" : "=r"(a) : "l"(p));
    return a;
}

#define CP_ASYNC16(dst_u32, src_ptr) \
    asm volatile("cp.async.cg.shared.global [%0], [%1], 16;" :: "r"(dst_u32), "l"(src_ptr))
#define CP_COMMIT() asm volatile("cp.async.commit_group;" ::: "memory")
#define CP_WAIT0()  asm volatile("cp.async.wait_group 0;" ::: "memory")

// ldmatrix x4: tf32 fragments (8x4 b32 quadrant == 8x8 b16 matrix)
#define LDSM_X4(r0, r1, r2, r3, addr) \
    asm volatile("ldmatrix.sync.aligned.m8n8.x4.shared.b16 {%0,%1,%2,%3}, [%4];" \
        : "=r"(r0), "=r"(r1), "=r"(r2), "=r"(r3) : "r"(addr))

__device__ __forceinline__ void mma_tf32_16n8k8(float* c, const uint32_t* a, const uint32_t* b) {
    asm volatile(
        "mma.sync.aligned.m16n8k8.row.col.f32.tf32.tf32.f32 "
        "{%0,%1,%2,%3}, {%4,%5,%6,%7}, {%8,%9}, {%0,%1,%2,%3};"
        : "+f"(c[0]), "+f"(c[1]), "+f"(c[2]), "+f"(c[3])
        : "r"(a[0]), "r"(a[1]), "r"(a[2]), "r"(a[3]), "r"(b[0]), "r"(b[1]));
}

// ---------------------------------------------------------------------------
// Fused prep kernel: round x (blocks [0,4096)); transpose+round Wqkv
// (blocks [4096,7168)); transpose+round Wout (blocks [7168,8192)).
// ---------------------------------------------------------------------------
__global__ __launch_bounds__(256) void prep(const float* __restrict__ x,
                                            const float* __restrict__ Wq,
                                            const float* __restrict__ Wo)
{
    __shared__ float t[32][33];
    const int b = blockIdx.x;
    const int tid = threadIdx.x;

    if (b < 4096) {
        int i = b * 256 + tid;
        float4 v = ((const float4*)x)[i];
        v.x = to_tf32(v.x); v.y = to_tf32(v.y); v.z = to_tf32(v.z); v.w = to_tf32(v.w);
        ((float4*)g_xr)[i] = v;
        return;
    }

    const int tx = tid & 31;
    const int ty = tid >> 5;

    if (b < 7168) {
        const int bb = b - 4096;
        const int f0 = (bb % 96) * 32;
        const int e0 = (bb / 96) * 32;
        const int h = f0 / 192, fin = f0 % 192;
        const float* src = Wq + (size_t)h * EE * 192;
#pragma unroll
        for (int i = 0; i < 4; i++)
            t[ty + 8*i][tx] = src[(size_t)(e0 + ty + 8*i) * 192 + fin + tx];
        __syncthreads();
#pragma unroll
        for (int i = 0; i < 4; i++)
            g_wtq[(size_t)(f0 + ty + 8*i) * EE + e0 + tx] = to_tf32(t[tx][ty + 8*i]);
    } else {
        const int bb = b - 7168;
        const int n0 = (bb % 32) * 32;
        const int k0 = (bb / 32) * 32;
#pragma unroll
        for (int i = 0; i < 4; i++)
            t[ty + 8*i][tx] = Wo[(size_t)(k0 + ty + 8*i) * EE + n0 + tx];
        __syncthreads();
#pragma unroll
        for (int i = 0; i < 4; i++)
            g_wto[(size_t)(n0 + ty + 8*i) * EE + k0 + tx] = to_tf32(t[tx][ty + 8*i]);
    }
}

// ---------------------------------------------------------------------------
// HMMA tf32 GEMM mainloop: CTA 128x128, 256 threads, 8 warps of 64x32.
// BK=32, cp.async double buffer, ONE __syncthreads per k-iter.
// Fragment loads via ldmatrix.x4 (stride 36 == 4 mod 32 -> conflict-free).
// ---------------------------------------------------------------------------
#define SM_AB_STRIDE 36
#define SM_STAGE (128*SM_AB_STRIDE)
#define GEMM_SMEM (4*SM_STAGE*4)

__device__ __forceinline__ void hmma_mainloop(uint32_t smu,
                                              const float* __restrict__ Ag,
                                              const float* __restrict__ Bg,
                                              float acc[4][4][4])
{
    const int tid = threadIdx.x;
    const uint32_t uA = smu;
    const uint32_t uB = smu + 2 * SM_STAGE * 4;

    const int lrow = tid >> 3;
    const int lc4  = tid & 7;

    auto issue = [&](int kt, int buf) {
#pragma unroll
        for (int j = 0; j < 4; j++) {
            int row = lrow + j * 32;
            uint32_t soff = (uint32_t)((buf * SM_STAGE + row * SM_AB_STRIDE + lc4 * 4) * 4);
            CP_ASYNC16(uA + soff, Ag + (size_t)row * EE + kt * 32 + lc4 * 4);
            CP_ASYNC16(uB + soff, Bg + (size_t)row * EE + kt * 32 + lc4 * 4);
        }
    };

    const int wid = tid >> 5;
    const int lane = tid & 31;
    const int wr = (wid & 1) * 64;
    const int wc = (wid >> 1) * 32;
    const int l7 = lane & 7;
    const int g1 = (lane >> 3) & 1;
    const int g2 = (lane >> 4) & 1;

    // ldmatrix per-thread base offsets (bytes)
    const uint32_t aoff = (uint32_t)(((wr + l7 + g1 * 8) * SM_AB_STRIDE + g2 * 4) * 4);
    const uint32_t boff = (uint32_t)(((wc + l7 + g2 * 8) * SM_AB_STRIDE + g1 * 4) * 4);

    issue(0, 0);
    CP_COMMIT();

#pragma unroll 1
    for (int kt = 0; kt < 32; kt++) {
        const int cur = kt & 1;
        CP_WAIT0();
        __syncthreads();
        if (kt < 31) { issue(kt + 1, cur ^ 1); CP_COMMIT(); }

        const uint32_t aB = uA + (uint32_t)(cur * SM_STAGE * 4) + aoff;
        const uint32_t bB = uB + (uint32_t)(cur * SM_STAGE * 4) + boff;

#pragma unroll
        for (int ks = 0; ks < 4; ks++) {
            const uint32_t kso = (uint32_t)(ks * 8 * 4);
            uint32_t af[4][4], bf[4][2];
#pragma unroll
            for (int i = 0; i < 4; i++)
                LDSM_X4(af[i][0], af[i][1], af[i][2], af[i][3],
                        aB + (uint32_t)(i * 16 * SM_AB_STRIDE * 4) + kso);
            LDSM_X4(bf[0][0], bf[0][1], bf[1][0], bf[1][1], bB + kso);
            LDSM_X4(bf[2][0], bf[2][1], bf[3][0], bf[3][1],
                    bB + (uint32_t)(16 * SM_AB_STRIDE * 4) + kso);
#pragma unroll
            for (int i = 0; i < 4; i++)
#pragma unroll
                for (int j = 0; j < 4; j++)
                    mma_tf32_16n8k8(acc[i][j], af[i], bf[j]);
        }
    }
}

// ---------------------------------------------------------------------------
// QKV GEMM (HMMA): + bias, tf32-round, scatter: K->g_k, Q->g_q, V->g_vt (transposed)
// ---------------------------------------------------------------------------
__global__ __launch_bounds__(256, 2) void qkv_mma(const float* __restrict__ bqkv)
{
    extern __shared__ float sm[];
    const uint32_t smu = s2u(sm);

    const int c0 = blockIdx.x * 128;
    const int r0 = blockIdx.y * 128;

    float acc[4][4][4];
#pragma unroll
    for (int i = 0; i < 4; i++)
#pragma unroll
        for (int j = 0; j < 4; j++)
#pragma unroll
            for (int t = 0; t < 4; t++) acc[i][j][t] = 0.f;

    hmma_mainloop(smu, g_xr + (size_t)r0 * EE, g_wtq + (size_t)c0 * EE, acc);

    const int wid = threadIdx.x >> 5;
    const int lane = threadIdx.x & 31;
    const int qr = lane >> 2, qc = lane & 3;
    const int wr = (wid & 1) * 64;
    const int wc = (wid >> 1) * 32;

#pragma unroll
    for (int i = 0; i < 4; i++) {
#pragma unroll
        for (int j = 0; j < 4; j++) {
            const int colF = c0 + wc + j * 8 + qc * 2;
            const int h = colF / 192, f = colF % 192;
            const int seg = f >> 6, fo = f & 63;
            const float b0 = bqkv[colF], b1 = bqkv[colF + 1];
#pragma unroll
            for (int half = 0; half < 2; half++) {
                const int r = r0 + wr + i * 16 + qr + half * 8;
                const int bb = r >> 11;
                const int n_ = r & (NN - 1);
                const float v0 = to_tf32(acc[i][j][half * 2 + 0] + b0);
                const float v1 = to_tf32(acc[i][j][half * 2 + 1] + b1);
                if (seg == 2) {
                    size_t vb = ((size_t)(bb * HH + h) * HD + fo) * NN + n_;
                    g_vt[vb] = v0;
                    g_vt[vb + NN] = v1;
                } else {
                    float* dst = (seg == 0) ? g_k : g_q;
                    size_t off = ((size_t)(bb * HH + h) * NN + n_) * HD + fo;
                    *(float2*)(dst + off) = make_float2(v0, v1);
                }
            }
        }
    }
}

// ---------------------------------------------------------------------------
// Output GEMM (HMMA): out = g_sa @ Wout + bout
// ---------------------------------------------------------------------------
__global__ __launch_bounds__(256, 2) void out_mma(const float* __restrict__ bout,
                                                  float* __restrict__ out)
{
    extern __shared__ float sm[];
    const uint32_t smu = s2u(sm);

    const int c0 = blockIdx.x * 128;
    const int r0 = blockIdx.y * 128;

    float acc[4][4][4];
#pragma unroll
    for (int i = 0; i < 4; i++)
#pragma unroll
        for (int j = 0; j < 4; j++)
#pragma unroll
            for (int t = 0; t < 4; t++) acc[i][j][t] = 0.f;

    hmma_mainloop(smu, g_sa + (size_t)r0 * EE, g_wto + (size_t)c0 * EE, acc);

    const int wid = threadIdx.x >> 5;
    const int lane = threadIdx.x & 31;
    const int qr = lane >> 2, qc = lane & 3;
    const int wr = (wid & 1) * 64;
    const int wc = (wid >> 1) * 32;

#pragma unroll
    for (int i = 0; i < 4; i++) {
#pragma unroll
        for (int j = 0; j < 4; j++) {
            const int col = c0 + wc + j * 8 + qc * 2;
            const float b0 = bout[col], b1 = bout[col + 1];
#pragma unroll
            for (int half = 0; half < 2; half++) {
                const size_t r = (size_t)(r0 + wr + i * 16 + qr + half * 8);
                float2 o;
                o.x = acc[i][j][half * 2 + 0] + b0;
                o.y = acc[i][j][half * 2 + 1] + b1;
                *(float2*)(out + r * EE + col) = o;
            }
        }
    }
}

// ---------------------------------------------------------------------------
// Causal flash attention, HMMA tf32, no online-max, ldmatrix fragments.
// CTA: 128 q-rows, 256 threads, 8 warps x 16 rows. K smem [j][e], V^T smem [d][j].
// Stride 68 == 4 (mod 32): ldmatrix conflict-free.
// ---------------------------------------------------------------------------
#define ASW 68
#define ATT_SMEM ((4*64*ASW + 128*ASW)*4)   // 104448 bytes

__global__ __launch_bounds__(256, 2) void attn_mma()
{
    extern __shared__ float sm[];
    const uint32_t uK = s2u(sm);
    const uint32_t uV = uK + 2 * 64 * ASW * 4;
    const uint32_t uP = uK + 4 * 64 * ASW * 4;
    float* Psm = sm + 4 * 64 * ASW;

    const int tid  = threadIdx.x;
    const int wid  = tid >> 5, lane = tid & 31;
    const int qr   = lane >> 2, qc = lane & 3;
    const int qt   = (int)gridDim.x - 1 - (int)blockIdx.x;   // heavy first
    const int bh   = blockIdx.y;
    const int wr   = wid * 16;

    const int l7 = lane & 7;
    const int g1 = (lane >> 3) & 1;
    const int g2 = (lane >> 4) & 1;
    // B-frag ldsm offsets (K and V tiles, stride ASW)
    const uint32_t boff = (uint32_t)(((l7 + g2 * 8) * ASW + g1 * 4) * 4);
    // P A-frag ldsm offset (warp-private rows)
    const uint32_t poff = (uint32_t)(((wr + l7 + g1 * 8) * ASW + g2 * 4) * 4);

    const float* kg = g_k  + (size_t)bh * NN * HD;
    const float* vg = g_vt + (size_t)bh * HD * NN;

    // Q fragments (g_q pre-rounded tf32; *0.125 exact power of 2)
    float qa[8][4];
    {
        const float* qb = g_q + ((size_t)bh * NN + qt * 128 + wr) * HD;
#pragma unroll
        for (int ks = 0; ks < 8; ks++) {
            qa[ks][0] = qb[qr * 64 + ks * 8 + qc] * 0.125f;
            qa[ks][1] = qb[(qr + 8) * 64 + ks * 8 + qc] * 0.125f;
            qa[ks][2] = qb[qr * 64 + ks * 8 + qc + 4] * 0.125f;
            qa[ks][3] = qb[(qr + 8) * 64 + ks * 8 + qc + 4] * 0.125f;
        }
    }

    float o[8][4];
#pragma unroll
    for (int nt = 0; nt < 8; nt++)
#pragma unroll
        for (int t = 0; t < 4; t++) o[nt][t] = 0.f;
    float l0 = 0.f, l1 = 0.f;

    const unsigned FULL = 0xffffffffu;
    const int jt_end = 2 * qt + 1;

    // cp.async one (K,V) stage: 64 rows x 64 floats each
    auto issue = [&](int jt) {
        const int buf = jt & 1;
#pragma unroll
        for (int i = 0; i < 4; i++) {
            int idx = tid + i * 256;            // 0..1023
            int row = idx >> 4;
            int c4  = (idx & 15) * 4;
            uint32_t soff = (uint32_t)((buf * 64 * ASW + row * ASW + c4) * 4);
            CP_ASYNC16(uK + soff, kg + (size_t)(jt * 64 + row) * HD + c4);
            CP_ASYNC16(uV + soff, vg + (size_t)row * NN + jt * 64 + c4);
        }
        CP_COMMIT();
    };

    issue(0);

#pragma unroll 1
    for (int jt = 0; jt <= jt_end; jt++) {
        CP_WAIT0();
        __syncthreads();
        if (jt < jt_end) issue(jt + 1);

        const uint32_t kB = uK + (uint32_t)((jt & 1) * 64 * ASW * 4) + boff;
        const uint32_t vB = uV + (uint32_t)((jt & 1) * 64 * ASW * 4) + boff;

        const bool active = (jt * 64 <= qt * 128 + wr + 15);
        if (active) {
            // ---- S = Q K^T ----
            float s[8][4];
#pragma unroll
            for (int nt = 0; nt < 8; nt++)
#pragma unroll
                for (int t = 0; t < 4; t++) s[nt][t] = 0.f;

#pragma unroll
            for (int ks = 0; ks < 8; ks++) {
                const uint32_t kso = (uint32_t)(ks * 8 * 4);
                uint32_t bf[8][2];
#pragma unroll
                for (int jp = 0; jp < 4; jp++)
                    LDSM_X4(bf[2*jp][0], bf[2*jp][1], bf[2*jp+1][0], bf[2*jp+1][1],
                            kB + (uint32_t)(jp * 16 * ASW * 4) + kso);
#pragma unroll
                for (int nt = 0; nt < 8; nt++)
                    mma_tf32_16n8k8(s[nt], (const uint32_t*)qa[ks], bf[nt]);
            }

            // ---- causal mask (tiles straddling diagonal) ----
            if (jt >= 2 * qt) {
                const int rg0 = qt * 128 + wr + qr;
                const int rg1 = rg0 + 8;
#pragma unroll
                for (int nt = 0; nt < 8; nt++) {
                    const int jg = jt * 64 + nt * 8 + 2 * qc;
                    if (jg > rg0)     s[nt][0] = -INFINITY;
                    if (jg + 1 > rg0) s[nt][1] = -INFINITY;
                    if (jg > rg1)     s[nt][2] = -INFINITY;
                    if (jg + 1 > rg1) s[nt][3] = -INFINITY;
                }
            }

            // ---- softmax numerator (no max-shift; scores bounded) ----
            float ps0 = 0.f, ps1 = 0.f;
#pragma unroll
            for (int nt = 0; nt < 8; nt++) {
                s[nt][0] = __expf(s[nt][0]);
                s[nt][1] = __expf(s[nt][1]);
                s[nt][2] = __expf(s[nt][2]);
                s[nt][3] = __expf(s[nt][3]);
                ps0 += s[nt][0] + s[nt][1];
                ps1 += s[nt][2] + s[nt][3];
            }
            ps0 += __shfl_xor_sync(FULL, ps0, 1);
            ps0 += __shfl_xor_sync(FULL, ps0, 2);
            ps1 += __shfl_xor_sync(FULL, ps1, 1);
            ps1 += __shfl_xor_sync(FULL, ps1, 2);
            l0 += ps0;
            l1 += ps1;

            // ---- write P to warp-private smem rows (tf32-rounded) ----
#pragma unroll
            for (int nt = 0; nt < 8; nt++) {
                *(float2*)&Psm[(wr + qr) * ASW + nt * 8 + 2 * qc] =
                    make_float2(to_tf32(s[nt][0]), to_tf32(s[nt][1]));
                *(float2*)&Psm[(wr + qr + 8) * ASW + nt * 8 + 2 * qc] =
                    make_float2(to_tf32(s[nt][2]), to_tf32(s[nt][3]));
            }
            __syncwarp();

            // ---- O += P V  (A via ldsm from Psm, B via ldsm from V^T tile) ----
#pragma unroll
            for (int ks = 0; ks < 8; ks++) {
                const uint32_t kso = (uint32_t)(ks * 8 * 4);
                uint32_t af[4];
                LDSM_X4(af[0], af[1], af[2], af[3], uP + poff + kso);
                uint32_t bf[8][2];
#pragma unroll
                for (int dp = 0; dp < 4; dp++)
                    LDSM_X4(bf[2*dp][0], bf[2*dp][1], bf[2*dp+1][0], bf[2*dp+1][1],
                            vB + (uint32_t)(dp * 16 * ASW * 4) + kso);
#pragma unroll
                for (int nt = 0; nt < 8; nt++)
                    mma_tf32_16n8k8(o[nt], af, bf[nt]);
            }
        }
    }

    // ---- epilogue: normalize + scatter to g_sa [B, N, E] (tf32-rounded) ----
    const float il0 = 1.0f / l0;
    const float il1 = 1.0f / l1;
    const int b = bh >> 4;
    const int h = bh & 15;
    const int n0 = qt * 128 + wr + qr;
    float* o0 = g_sa + ((size_t)b * NN + n0) * EE + h * HD;
    float* o1 = o0 + (size_t)8 * EE;
#pragma unroll
    for (int nt = 0; nt < 8; nt++) {
        const int d = nt * 8 + 2 * qc;
        *(float2*)(o0 + d) = make_float2(to_tf32(o[nt][0] * il0), to_tf32(o[nt][1] * il0));
        *(float2*)(o1 + d) = make_float2(to_tf32(o[nt][2] * il1), to_tf32(o[nt][3] * il1));
    }
}

// ---------------------------------------------------------------------------
extern "C" void kernel_launch(void* const* d_in, const int* in_sizes, int n_in,
                              void* d_out, int out_size)
{
    const float* x    = (const float*)d_in[0];
    const float* Wqkv = (const float*)d_in[1];
    const float* bqkv = (const float*)d_in[2];
    const float* Wout = (const float*)d_in[3];
    const float* bout = (const float*)d_in[4];
    float* out = (float*)d_out;

    // 0) fused prep: round x, transpose+round weights
    prep<<<8192, 256>>>(x, Wqkv, Wout);

    // 1) QKV projection (HMMA tf32 + ldmatrix)
    cudaFuncSetAttribute(qkv_mma, cudaFuncAttributeMaxDynamicSharedMemorySize, GEMM_SMEM);
    qkv_mma<<<dim3(FF / 128, ROWS / 128), 256, GEMM_SMEM>>>(bqkv);

    // 2) Causal attention (HMMA tf32 + ldmatrix)
    cudaFuncSetAttribute(attn_mma, cudaFuncAttributeMaxDynamicSharedMemorySize, ATT_SMEM);
    attn_mma<<<dim3(NN / 128, BB * HH), 256, ATT_SMEM>>>();

    // 3) Output projection (HMMA tf32 + ldmatrix)
    cudaFuncSetAttribute(out_mma, cudaFuncAttributeMaxDynamicSharedMemorySize, GEMM_SMEM);
    out_mma<<<dim3(EE / 128, ROWS / 128), 256, GEMM_SMEM>>>(bout, out);
}

// round 15
// speedup vs baseline: 5.9880x; 1.2500x over previous
#include <cuda_runtime.h>
#include <cuda_fp16.h>
#include <math.h>
#include <stdint.h>

// Problem constants
#define BB 2
#define NN 2048
#define EE 1024
#define HH 16
#define HD 64
#define ROWS (BB*NN)          // 4096
#define FF (3*HH*HD)          // 3072

// Scratch (device globals; no allocations allowed)
__device__ __half g_kh[BB*HH*NN*HD];
__device__ __half g_qh[BB*HH*NN*HD];   // pre-scaled by 0.125
__device__ __half g_vth[BB*HH*HD*NN];  // V transposed: [bh][d][n]
__device__ __half g_sah[BB*NN*EE];
__device__ __half g_xh[ROWS*EE];       // x rounded to fp16
__device__ __half g_wqh[FF*EE];        // Wqkv transposed [F][E], fp16
__device__ __half g_woh[EE*EE];        // Wout transposed [n][k], fp16

// ---------------------------------------------------------------------------
// helpers
// ---------------------------------------------------------------------------
__device__ __forceinline__ uint32_t s2u(const void* p) {
    uint32_t a;
    asm("{ .reg .u64 t; cvta.to.shared.u64 t, %1; cvt.u32.u64 %0, t; }" : "=r"(a) : "l"(p));
    return a;
}
__device__ __forceinline__ uint32_t packh2(float lo, float hi) {
    __half2 h = __floats2half2_rn(lo, hi);
    return *(uint32_t*)&h;
}

#define CP_ASYNC16(dst_u32, src_ptr) \
    asm volatile("cp.async.cg.shared.global [%0], [%1], 16;" :: "r"(dst_u32), "l"(src_ptr))
#define CP_COMMIT() asm volatile("cp.async.commit_group;" ::: "memory")
#define CP_WAIT0()  asm volatile("cp.async.wait_group 0;" ::: "memory")

#define LDSM_X4(r0, r1, r2, r3, addr) \
    asm volatile("ldmatrix.sync.aligned.m8n8.x4.shared.b16 {%0,%1,%2,%3}, [%4];" \
        : "=r"(r0), "=r"(r1), "=r"(r2), "=r"(r3) : "r"(addr))

__device__ __forceinline__ void mma_f16(float* c, const uint32_t* a, const uint32_t* b) {
    asm volatile(
        "mma.sync.aligned.m16n8k16.row.col.f32.f16.f16.f32 "
        "{%0,%1,%2,%3}, {%4,%5,%6,%7}, {%8,%9}, {%0,%1,%2,%3};"
        : "+f"(c[0]), "+f"(c[1]), "+f"(c[2]), "+f"(c[3])
        : "r"(a[0]), "r"(a[1]), "r"(a[2]), "r"(a[3]), "r"(b[0]), "r"(b[1]));
}

// ---------------------------------------------------------------------------
// Fused prep: x->fp16 (blocks [0,4096)); Wqkv transpose->fp16 ([4096,7168));
// Wout transpose->fp16 ([7168,8192)).
// ---------------------------------------------------------------------------
__global__ __launch_bounds__(256) void prep(const float* __restrict__ x,
                                            const float* __restrict__ Wq,
                                            const float* __restrict__ Wo)
{
    __shared__ float t[32][33];
    const int b = blockIdx.x;
    const int tid = threadIdx.x;

    if (b < 4096) {
        int i = b * 256 + tid;                        // float4 index
        float4 v = ((const float4*)x)[i];
        uint2 o;
        o.x = packh2(v.x, v.y);
        o.y = packh2(v.z, v.w);
        ((uint2*)g_xh)[i] = o;
        return;
    }

    const int tx = tid & 31;
    const int ty = tid >> 5;

    if (b < 7168) {
        const int bb = b - 4096;
        const int f0 = (bb % 96) * 32;
        const int e0 = (bb / 96) * 32;
        const int h = f0 / 192, fin = f0 % 192;
        const float* src = Wq + (size_t)h * EE * 192;
#pragma unroll
        for (int i = 0; i < 4; i++)
            t[ty + 8*i][tx] = src[(size_t)(e0 + ty + 8*i) * 192 + fin + tx];
        __syncthreads();
#pragma unroll
        for (int i = 0; i < 4; i++)
            g_wqh[(size_t)(f0 + ty + 8*i) * EE + e0 + tx] = __float2half_rn(t[tx][ty + 8*i]);
    } else {
        const int bb = b - 7168;
        const int n0 = (bb % 32) * 32;
        const int k0 = (bb / 32) * 32;
#pragma unroll
        for (int i = 0; i < 4; i++)
            t[ty + 8*i][tx] = Wo[(size_t)(k0 + ty + 8*i) * EE + n0 + tx];
        __syncthreads();
#pragma unroll
        for (int i = 0; i < 4; i++)
            g_woh[(size_t)(n0 + ty + 8*i) * EE + k0 + tx] = __float2half_rn(t[tx][ty + 8*i]);
    }
}

// ---------------------------------------------------------------------------
// fp16 HMMA GEMM mainloop: CTA 128x128, 256 threads, 8 warps of 64x32.
// BK=64 halves, cp.async double buffer, one __syncthreads per k-iter.
// smem stride 72 halves (144B): ldmatrix rows hit 8 distinct 16B chunks.
// ---------------------------------------------------------------------------
#define SM_STRIDE 72
#define SM_STAGE_B (128*SM_STRIDE*2)          // bytes per matrix per stage (18432)
#define GEMM_SMEM (4*SM_STAGE_B)              // 73728

__device__ __forceinline__ void hmma_mainloop(uint32_t smu,
                                              const __half* __restrict__ Ag,
                                              const __half* __restrict__ Bg,
                                              float acc[4][4][4])
{
    const int tid = threadIdx.x;
    const uint32_t uA = smu;
    const uint32_t uB = smu + 2 * SM_STAGE_B;

    const int lrow = tid >> 3;          // 0..31
    const int lc8  = tid & 7;           // 16B chunk (8 halves)

    auto issue = [&](int kt, int buf) {
#pragma unroll
        for (int j = 0; j < 4; j++) {
            int row = lrow + j * 32;
            uint32_t soff = (uint32_t)(buf * SM_STAGE_B + row * (SM_STRIDE*2) + lc8 * 16);
            CP_ASYNC16(uA + soff, Ag + (size_t)row * EE + kt * 64 + lc8 * 8);
            CP_ASYNC16(uB + soff, Bg + (size_t)row * EE + kt * 64 + lc8 * 8);
        }
    };

    const int wid = tid >> 5;
    const int lane = tid & 31;
    const int wr = (wid & 1) * 64;
    const int wc = (wid >> 1) * 32;
    const int l7 = lane & 7;
    const int g1 = (lane >> 3) & 1;
    const int g2 = (lane >> 4) & 1;

    // ldmatrix per-thread base byte offsets
    const uint32_t aoff = (uint32_t)((wr + l7 + g1 * 8) * (SM_STRIDE*2) + g2 * 16);
    const uint32_t boff = (uint32_t)((wc + l7 + g2 * 8) * (SM_STRIDE*2) + g1 * 16);

    issue(0, 0);
    CP_COMMIT();

#pragma unroll 1
    for (int kt = 0; kt < 16; kt++) {
        const int cur = kt & 1;
        CP_WAIT0();
        __syncthreads();
        if (kt < 15) { issue(kt + 1, cur ^ 1); CP_COMMIT(); }

        const uint32_t aB = uA + (uint32_t)(cur * SM_STAGE_B) + aoff;
        const uint32_t bB = uB + (uint32_t)(cur * SM_STAGE_B) + boff;

#pragma unroll
        for (int ks = 0; ks < 4; ks++) {
            const uint32_t kso = (uint32_t)(ks * 32);      // 16 halves
            uint32_t af[4][4], bf[4][2];
#pragma unroll
            for (int i = 0; i < 4; i++)
                LDSM_X4(af[i][0], af[i][1], af[i][2], af[i][3],
                        aB + (uint32_t)(i * 16 * SM_STRIDE * 2) + kso);
            LDSM_X4(bf[0][0], bf[0][1], bf[1][0], bf[1][1], bB + kso);
            LDSM_X4(bf[2][0], bf[2][1], bf[3][0], bf[3][1],
                    bB + (uint32_t)(16 * SM_STRIDE * 2) + kso);
#pragma unroll
            for (int i = 0; i < 4; i++)
#pragma unroll
                for (int j = 0; j < 4; j++)
                    mma_f16(acc[i][j], af[i], bf[j]);
        }
    }
}

// ---------------------------------------------------------------------------
// QKV GEMM: + bias, fp16-round, scatter: K->g_kh, Q->g_qh (x0.125), V->g_vth^T
// ---------------------------------------------------------------------------
__global__ __launch_bounds__(256, 2) void qkv_mma(const float* __restrict__ bqkv)
{
    extern __shared__ char smc[];
    const uint32_t smu = s2u(smc);

    const int c0 = blockIdx.x * 128;
    const int r0 = blockIdx.y * 128;

    float acc[4][4][4];
#pragma unroll
    for (int i = 0; i < 4; i++)
#pragma unroll
        for (int j = 0; j < 4; j++)
#pragma unroll
            for (int t = 0; t < 4; t++) acc[i][j][t] = 0.f;

    hmma_mainloop(smu, g_xh + (size_t)r0 * EE, g_wqh + (size_t)c0 * EE, acc);

    const int wid = threadIdx.x >> 5;
    const int lane = threadIdx.x & 31;
    const int qr = lane >> 2, qc = lane & 3;
    const int wr = (wid & 1) * 64;
    const int wc = (wid >> 1) * 32;

#pragma unroll
    for (int i = 0; i < 4; i++) {
#pragma unroll
        for (int j = 0; j < 4; j++) {
            const int colF = c0 + wc + j * 8 + qc * 2;
            const int h = colF / 192, f = colF % 192;
            const int seg = f >> 6, fo = f & 63;
            const float b0 = bqkv[colF], b1 = bqkv[colF + 1];
#pragma unroll
            for (int half = 0; half < 2; half++) {
                const int r = r0 + wr + i * 16 + qr + half * 8;
                const int bb = r >> 11;
                const int n_ = r & (NN - 1);
                float v0 = acc[i][j][half * 2 + 0] + b0;
                float v1 = acc[i][j][half * 2 + 1] + b1;
                if (seg == 2) {
                    size_t vb = ((size_t)(bb * HH + h) * HD + fo) * NN + n_;
                    g_vth[vb]      = __float2half_rn(v0);
                    g_vth[vb + NN] = __float2half_rn(v1);
                } else {
                    size_t off = ((size_t)(bb * HH + h) * NN + n_) * HD + fo;
                    if (seg == 0) {
                        *(uint32_t*)(g_kh + off) = packh2(v0, v1);
                    } else {
                        *(uint32_t*)(g_qh + off) = packh2(v0 * 0.125f, v1 * 0.125f);
                    }
                }
            }
        }
    }
}

// ---------------------------------------------------------------------------
// Output GEMM: out = g_sah @ Wout + bout (fp32 out)
// ---------------------------------------------------------------------------
__global__ __launch_bounds__(256, 2) void out_mma(const float* __restrict__ bout,
                                                  float* __restrict__ out)
{
    extern __shared__ char smc[];
    const uint32_t smu = s2u(smc);

    const int c0 = blockIdx.x * 128;
    const int r0 = blockIdx.y * 128;

    float acc[4][4][4];
#pragma unroll
    for (int i = 0; i < 4; i++)
#pragma unroll
        for (int j = 0; j < 4; j++)
#pragma unroll
            for (int t = 0; t < 4; t++) acc[i][j][t] = 0.f;

    hmma_mainloop(smu, g_sah + (size_t)r0 * EE, g_woh + (size_t)c0 * EE, acc);

    const int wid = threadIdx.x >> 5;
    const int lane = threadIdx.x & 31;
    const int qr = lane >> 2, qc = lane & 3;
    const int wr = (wid & 1) * 64;
    const int wc = (wid >> 1) * 32;

#pragma unroll
    for (int i = 0; i < 4; i++) {
#pragma unroll
        for (int j = 0; j < 4; j++) {
            const int col = c0 + wc + j * 8 + qc * 2;
            const float b0 = bout[col], b1 = bout[col + 1];
#pragma unroll
            for (int half = 0; half < 2; half++) {
                const size_t r = (size_t)(r0 + wr + i * 16 + qr + half * 8);
                float2 o;
                o.x = acc[i][j][half * 2 + 0] + b0;
                o.y = acc[i][j][half * 2 + 1] + b1;
                *(float2*)(out + r * EE + col) = o;
            }
        }
    }
}

// ---------------------------------------------------------------------------
// Causal flash attention, fp16 HMMA, online softmax (needed: P must fit fp16),
// P passes C-frag -> A-frag in registers (no smem round-trip).
// CTA: 128 q-rows, 256 threads, 8 warps x 16 rows.
// K smem [j][k] (64x72h), V^T smem [d][j] (64x72h), double buffered.
// ---------------------------------------------------------------------------
#define ASW 72
#define ATT_STAGE_B (64*ASW*2)               // 9216 bytes
#define ATT_SMEM (4*ATT_STAGE_B)             // 36864

__global__ __launch_bounds__(256, 2) void attn_mma()
{
    extern __shared__ char smc[];
    const uint32_t uK = s2u(smc);
    const uint32_t uV = uK + 2 * ATT_STAGE_B;

    const int tid  = threadIdx.x;
    const int wid  = tid >> 5, lane = tid & 31;
    const int qr   = lane >> 2, qc = lane & 3;
    const int qt   = (int)gridDim.x - 1 - (int)blockIdx.x;   // heavy first
    const int bh   = blockIdx.y;
    const int wr   = wid * 16;

    const int l7 = lane & 7;
    const int g1 = (lane >> 3) & 1;
    const int g2 = (lane >> 4) & 1;
    const uint32_t boff = (uint32_t)((l7 + g2 * 8) * (ASW*2) + g1 * 16);

    const __half* kg = g_kh  + (size_t)bh * NN * HD;
    const __half* vg = g_vth + (size_t)bh * HD * NN;

    // Q A-fragments (pre-scaled fp16): 4 k16 chunks x 4 regs
    uint32_t qa[4][4];
    {
        const __half* qb = g_qh + ((size_t)bh * NN + qt * 128 + wr) * HD;
#pragma unroll
        for (int ks = 0; ks < 4; ks++) {
            qa[ks][0] = *(const uint32_t*)(qb + qr * 64 + ks * 16 + 2 * qc);
            qa[ks][1] = *(const uint32_t*)(qb + (qr + 8) * 64 + ks * 16 + 2 * qc);
            qa[ks][2] = *(const uint32_t*)(qb + qr * 64 + ks * 16 + 2 * qc + 8);
            qa[ks][3] = *(const uint32_t*)(qb + (qr + 8) * 64 + ks * 16 + 2 * qc + 8);
        }
    }

    float o[8][4];
#pragma unroll
    for (int nt = 0; nt < 8; nt++)
#pragma unroll
        for (int t = 0; t < 4; t++) o[nt][t] = 0.f;
    float m0 = -INFINITY, m1 = -INFINITY, l0 = 0.f, l1 = 0.f;

    const unsigned FULL = 0xffffffffu;
    const int jt_end = 2 * qt + 1;

    // cp.async one (K,V) stage: 64 rows x 64 halves each
    auto issue = [&](int jt) {
        const int buf = jt & 1;
#pragma unroll
        for (int i = 0; i < 2; i++) {
            int idx = tid + i * 256;            // 0..511
            int row = idx >> 3;                 // 0..63
            int c8  = idx & 7;
            uint32_t soff = (uint32_t)(buf * ATT_STAGE_B + row * (ASW*2) + c8 * 16);
            CP_ASYNC16(uK + soff, kg + (size_t)(jt * 64 + row) * HD + c8 * 8);
            CP_ASYNC16(uV + soff, vg + (size_t)row * NN + jt * 64 + c8 * 8);
        }
        CP_COMMIT();
    };

    issue(0);

#pragma unroll 1
    for (int jt = 0; jt <= jt_end; jt++) {
        CP_WAIT0();
        __syncthreads();
        if (jt < jt_end) issue(jt + 1);

        const uint32_t kB = uK + (uint32_t)((jt & 1) * ATT_STAGE_B) + boff;
        const uint32_t vB = uV + (uint32_t)((jt & 1) * ATT_STAGE_B) + boff;

        const bool active = (jt * 64 <= qt * 128 + wr + 15);
        if (active) {
            // ---- S = Q K^T ----
            float s[8][4];
#pragma unroll
            for (int nt = 0; nt < 8; nt++)
#pragma unroll
                for (int t = 0; t < 4; t++) s[nt][t] = 0.f;

#pragma unroll
            for (int ks = 0; ks < 4; ks++) {
                const uint32_t kso = (uint32_t)(ks * 32);
                uint32_t bf[8][2];
#pragma unroll
                for (int jp = 0; jp < 4; jp++)
                    LDSM_X4(bf[2*jp][0], bf[2*jp][1], bf[2*jp+1][0], bf[2*jp+1][1],
                            kB + (uint32_t)(jp * 16 * ASW * 2) + kso);
#pragma unroll
                for (int nt = 0; nt < 8; nt++)
                    mma_f16(s[nt], qa[ks], bf[nt]);
            }

            // ---- causal mask ----
            if (jt >= 2 * qt) {
                const int rg0 = qt * 128 + wr + qr;
                const int rg1 = rg0 + 8;
#pragma unroll
                for (int nt = 0; nt < 8; nt++) {
                    const int jg = jt * 64 + nt * 8 + 2 * qc;
                    if (jg > rg0)     s[nt][0] = -INFINITY;
                    if (jg + 1 > rg0) s[nt][1] = -INFINITY;
                    if (jg > rg1)     s[nt][2] = -INFINITY;
                    if (jg + 1 > rg1) s[nt][3] = -INFINITY;
                }
            }

            // ---- online softmax (rows qr / qr+8; quad shfl) ----
            float mt0 = s[0][0], mt1 = s[0][2];
#pragma unroll
            for (int nt = 0; nt < 8; nt++) {
                mt0 = fmaxf(mt0, fmaxf(s[nt][0], s[nt][1]));
                mt1 = fmaxf(mt1, fmaxf(s[nt][2], s[nt][3]));
            }
            mt0 = fmaxf(mt0, __shfl_xor_sync(FULL, mt0, 1));
            mt0 = fmaxf(mt0, __shfl_xor_sync(FULL, mt0, 2));
            mt1 = fmaxf(mt1, __shfl_xor_sync(FULL, mt1, 1));
            mt1 = fmaxf(mt1, __shfl_xor_sync(FULL, mt1, 2));

            const float mn0 = fmaxf(m0, mt0);
            const float mn1 = fmaxf(m1, mt1);
            const float c0_ = __expf(m0 - mn0);
            const float c1_ = __expf(m1 - mn1);

            float ps0 = 0.f, ps1 = 0.f;
#pragma unroll
            for (int nt = 0; nt < 8; nt++) {
                s[nt][0] = __expf(s[nt][0] - mn0);
                s[nt][1] = __expf(s[nt][1] - mn0);
                s[nt][2] = __expf(s[nt][2] - mn1);
                s[nt][3] = __expf(s[nt][3] - mn1);
                ps0 += s[nt][0] + s[nt][1];
                ps1 += s[nt][2] + s[nt][3];
            }
            ps0 += __shfl_xor_sync(FULL, ps0, 1);
            ps0 += __shfl_xor_sync(FULL, ps0, 2);
            ps1 += __shfl_xor_sync(FULL, ps1, 1);
            ps1 += __shfl_xor_sync(FULL, ps1, 2);

            l0 = l0 * c0_ + ps0;  m0 = mn0;
            l1 = l1 * c1_ + ps1;  m1 = mn1;
#pragma unroll
            for (int nt = 0; nt < 8; nt++) {
                o[nt][0] *= c0_;  o[nt][1] *= c0_;
                o[nt][2] *= c1_;  o[nt][3] *= c1_;
            }

            // ---- O += P V : P packs C-frag -> A-frag in registers ----
#pragma unroll
            for (int ks = 0; ks < 4; ks++) {
                uint32_t af[4];
                af[0] = packh2(s[2*ks][0],   s[2*ks][1]);
                af[1] = packh2(s[2*ks][2],   s[2*ks][3]);
                af[2] = packh2(s[2*ks+1][0], s[2*ks+1][1]);
                af[3] = packh2(s[2*ks+1][2], s[2*ks+1][3]);
                const uint32_t kso = (uint32_t)(ks * 32);
                uint32_t bf[8][2];
#pragma unroll
                for (int dp = 0; dp < 4; dp++)
                    LDSM_X4(bf[2*dp][0], bf[2*dp][1], bf[2*dp+1][0], bf[2*dp+1][1],
                            vB + (uint32_t)(dp * 16 * ASW * 2) + kso);
#pragma unroll
                for (int nt = 0; nt < 8; nt++)
                    mma_f16(o[nt], af, bf[nt]);
            }
        }
    }

    // ---- epilogue: normalize + scatter to g_sah [B, N, E] ----
    const float il0 = 1.0f / l0;
    const float il1 = 1.0f / l1;
    const int b = bh >> 4;
    const int h = bh & 15;
    const int n0 = qt * 128 + wr + qr;
    __half* o0 = g_sah + ((size_t)b * NN + n0) * EE + h * HD;
    __half* o1 = o0 + (size_t)8 * EE;
#pragma unroll
    for (int nt = 0; nt < 8; nt++) {
        const int d = nt * 8 + 2 * qc;
        *(uint32_t*)(o0 + d) = packh2(o[nt][0] * il0, o[nt][1] * il0);
        *(uint32_t*)(o1 + d) = packh2(o[nt][2] * il1, o[nt][3] * il1);
    }
}

// ---------------------------------------------------------------------------
extern "C" void kernel_launch(void* const* d_in, const int* in_sizes, int n_in,
                              void* d_out, int out_size)
{
    const float* x    = (const float*)d_in[0];
    const float* Wqkv = (const float*)d_in[1];
    const float* bqkv = (const float*)d_in[2];
    const float* Wout = (const float*)d_in[3];
    const float* bout = (const float*)d_in[4];
    float* out = (float*)d_out;

    // 0) fused prep: round x + transpose weights to fp16
    prep<<<8192, 256>>>(x, Wqkv, Wout);

    // 1) QKV projection (fp16 HMMA)
    cudaFuncSetAttribute(qkv_mma, cudaFuncAttributeMaxDynamicSharedMemorySize, GEMM_SMEM);
    qkv_mma<<<dim3(FF / 128, ROWS / 128), 256, GEMM_SMEM>>>(bqkv);

    // 2) Causal attention (fp16 HMMA)
    cudaFuncSetAttribute(attn_mma, cudaFuncAttributeMaxDynamicSharedMemorySize, ATT_SMEM);
    attn_mma<<<dim3(NN / 128, BB * HH), 256, ATT_SMEM>>>();

    // 3) Output projection (fp16 HMMA)
    cudaFuncSetAttribute(out_mma, cudaFuncAttributeMaxDynamicSharedMemorySize, GEMM_SMEM);
    out_mma<<<dim3(EE / 128, ROWS / 128), 256, GEMM_SMEM>>>(bout, out);
}